// round 11
// baseline (speedup 1.0000x reference)
#include <cuda_runtime.h>
#include <cuda_bf16.h>
#include <cstdint>
#include <math.h>

namespace {
constexpr int kB   = 4;
constexpr int kLq  = 512;
constexpr int kLkv = 2048;
constexpr int kDim = 1024;
constexpr int kH   = 16;
constexpr int kMlp = 4096;
constexpr int kNQ  = kB * kLq;    // 2048
constexpr int kNKV = kB * kLkv;   // 8192
}

__device__ __align__(256) unsigned char g_scratch[160u * 1024u * 1024u];

#define CP_ASYNC16(dst, src) \
    asm volatile("cp.async.cg.shared.global [%0], [%1], 16;" :: "r"(dst), "l"(src))
#define CP_COMMIT() asm volatile("cp.async.commit_group;")
#define LDSM4(r0,r1,r2,r3,addr) \
    asm volatile("ldmatrix.sync.aligned.m8n8.x4.shared.b16 {%0,%1,%2,%3}, [%4];" \
        : "=r"(r0),"=r"(r1),"=r"(r2),"=r"(r3) : "r"(addr))
#define LDSM4T(r0,r1,r2,r3,addr) \
    asm volatile("ldmatrix.sync.aligned.m8n8.x4.trans.shared.b16 {%0,%1,%2,%3}, [%4];" \
        : "=r"(r0),"=r"(r1),"=r"(r2),"=r"(r3) : "r"(addr))
#define MMA16816(d,a0,a1,a2,a3,b0,b1) \
    asm volatile("mma.sync.aligned.m16n8k16.row.col.f32.bf16.bf16.f32 " \
        "{%0,%1,%2,%3}, {%4,%5,%6,%7}, {%8,%9}, {%0,%1,%2,%3};" \
        : "+f"(d[0]),"+f"(d[1]),"+f"(d[2]),"+f"(d[3]) \
        : "r"(a0),"r"(a1),"r"(a2),"r"(a3),"r"(b0),"r"(b1))

__device__ __forceinline__ uint32_t pack_bf16(float a, float b) {
    __nv_bfloat162 t = __floats2bfloat162_rn(a, b);
    return *reinterpret_cast<uint32_t*>(&t);
}

// ---------------------------------------------------------------------------
// Merged f32 -> bf16 weight convert
// ---------------------------------------------------------------------------
__global__ __launch_bounds__(256) void cvt_all_kernel(
    const float* __restrict__ Wq, const float* __restrict__ Wk,
    const float* __restrict__ Wv, const float* __restrict__ Wo,
    const float* __restrict__ fc1, const float* __restrict__ fc2,
    __nv_bfloat16* __restrict__ dst)
{
    const size_t M1 = 1u << 20;
    size_t gid = (size_t)blockIdx.x * 1024 + threadIdx.x * 4;
    const float* src; size_t off;
    if (gid < 4 * M1) {
        int si = (int)(gid >> 20);
        src = (si == 0) ? Wq : (si == 1) ? Wk : (si == 2) ? Wv : Wo;
        off = gid & (M1 - 1);
    } else if (gid < 8 * M1) { src = fc1; off = gid - 4 * M1; }
    else                     { src = fc2; off = gid - 8 * M1; }
    float4 v = *reinterpret_cast<const float4*>(src + off);
    *reinterpret_cast<__nv_bfloat162*>(dst + gid)     = __floats2bfloat162_rn(v.x, v.y);
    *reinterpret_cast<__nv_bfloat162*>(dst + gid + 2) = __floats2bfloat162_rn(v.z, v.w);
}

// ---------------------------------------------------------------------------
// LayerNorm core (fp32 -> bf16), one block per row
// ---------------------------------------------------------------------------
__device__ __forceinline__ void ln_row(
    const float* __restrict__ xr, const float* __restrict__ wv4,
    const float* __restrict__ bv4, __nv_bfloat16* __restrict__ yr)
{
    int t = threadIdx.x;
    float4 xv = reinterpret_cast<const float4*>(xr)[t];
    float s  = xv.x + xv.y + xv.z + xv.w;
    float s2 = xv.x*xv.x + xv.y*xv.y + xv.z*xv.z + xv.w*xv.w;

    #pragma unroll
    for (int off = 16; off > 0; off >>= 1) {
        s  += __shfl_xor_sync(0xffffffffu, s,  off);
        s2 += __shfl_xor_sync(0xffffffffu, s2, off);
    }
    __shared__ float rs[8], rs2[8];
    int wid = t >> 5;
    if ((t & 31) == 0) { rs[wid] = s; rs2[wid] = s2; }
    __syncthreads();
    s = 0.f; s2 = 0.f;
    #pragma unroll
    for (int i = 0; i < 8; i++) { s += rs[i]; s2 += rs2[i]; }

    float mu  = s * (1.0f / kDim);
    float var = s2 * (1.0f / kDim) - mu * mu;
    float r   = rsqrtf(var + 1e-6f);

    float4 wv = reinterpret_cast<const float4*>(wv4)[t];
    float4 bv = reinterpret_cast<const float4*>(bv4)[t];
    reinterpret_cast<__nv_bfloat162*>(yr)[2*t] =
        __floats2bfloat162_rn((xv.x - mu) * r * wv.x + bv.x,
                              (xv.y - mu) * r * wv.y + bv.y);
    reinterpret_cast<__nv_bfloat162*>(yr)[2*t+1] =
        __floats2bfloat162_rn((xv.z - mu) * r * wv.z + bv.z,
                              (xv.w - mu) * r * wv.w + bv.w);
}

__global__ __launch_bounds__(256) void ln_bf16_kernel(
    const float* __restrict__ x, const float* __restrict__ w,
    const float* __restrict__ b, __nv_bfloat16* __restrict__ y)
{
    int row = blockIdx.x;
    ln_row(x + (size_t)row * kDim, w, b, y + (size_t)row * kDim);
}

__global__ __launch_bounds__(256) void ln_qkv_kernel(
    const float* __restrict__ qx, const float* __restrict__ kvx,
    const float* __restrict__ qw, const float* __restrict__ qb_,
    const float* __restrict__ kvw, const float* __restrict__ kvb,
    __nv_bfloat16* __restrict__ qy, __nv_bfloat16* __restrict__ kvy)
{
    int row = blockIdx.x;
    if (row < kNQ) {
        ln_row(qx + (size_t)row * kDim, qw, qb_, qy + (size_t)row * kDim);
    } else {
        int r = row - kNQ;
        ln_row(kvx + (size_t)r * kDim, kvw, kvb, kvy + (size_t)r * kDim);
    }
}

// ---------------------------------------------------------------------------
// GEMM core: C[.,N] = A @ W^T.  BM threads (BM/32 warps, (BM/64)x2 layout),
// warp tile 64 x BN/2, BK=64, 3-stage cp.async, one barrier per k-iter.
// EPI 1: bf16 GELU(acc+bias).  EPI 2: fp32 res + alpha*(acc+bias).
// EPI 3: bf16, per-64-col L2-norm*scale if do_norm else plain.
// ---------------------------------------------------------------------------
template <int EPI, int BM, int BN>
__device__ __forceinline__ void gemm_core(
    const __nv_bfloat16* __restrict__ A, const __nv_bfloat16* __restrict__ W,
    int N, int K, long m0, long n0,
    const float* __restrict__ bias, const float* __restrict__ res,
    const float* __restrict__ alpha,
    float* __restrict__ Cf, __nv_bfloat16* __restrict__ Cb,
    bool do_norm, float nscale, uint32_t smem)
{
    constexpr int NW   = BN / 2;
    constexpr int NFR  = NW / 8;
    constexpr int NB16 = NW / 16;
    constexpr uint32_t kStageBytes = (uint32_t)(BM + BN) * 128u;
    constexpr uint32_t kBOff = (uint32_t)BM * 128u;
    constexpr int LITER = (BM + BN) * 8 / BM;   // BM threads

    const int tid  = threadIdx.x;
    const int lane = tid & 31;
    const int w    = tid >> 5;
    const int wr   = (w >> 1) * 64;
    const int wc   = (w & 1) * NW;

    const __nv_bfloat16* Ag = A + m0 * K;
    const __nv_bfloat16* Wg = W + n0 * K;

    auto load_tile = [&](int t, int s) {
        uint32_t sA = smem + (uint32_t)s * kStageBytes;
        uint32_t sB = sA + kBOff;
        const __nv_bfloat16* a = Ag + (long)t * 64;
        const __nv_bfloat16* b = Wg + (long)t * 64;
        #pragma unroll
        for (int p = 0; p < LITER; p++) {
            int idx = tid + p * BM;
            int row = idx >> 3, ch = idx & 7;
            if (row < BM) {
                uint32_t doff = row * 128 + ((uint32_t)(ch ^ (row & 7)) << 4);
                CP_ASYNC16(sA + doff, a + (long)row * K + ch * 8);
            } else {
                int r = row - BM;
                uint32_t doff = r * 128 + ((uint32_t)(ch ^ (r & 7)) << 4);
                CP_ASYNC16(sB + doff, b + (long)r * K + ch * 8);
            }
        }
    };

    float acc[4][NFR][4];
    #pragma unroll
    for (int i = 0; i < 4; i++)
        #pragma unroll
        for (int j = 0; j < NFR; j++)
            #pragma unroll
            for (int c = 0; c < 4; c++) acc[i][j][c] = 0.f;

    const int T = K >> 6;

    load_tile(0, 0); CP_COMMIT();
    load_tile(1, 1); CP_COMMIT();

    for (int kt = 0; kt < T; kt++) {
        int s = kt % 3;
        asm volatile("cp.async.wait_group 1;" ::: "memory");
        __syncthreads();

        if (kt + 2 < T) load_tile(kt + 2, (kt + 2) % 3);
        CP_COMMIT();

        uint32_t sA = smem + (uint32_t)s * kStageBytes;
        uint32_t sB = sA + kBOff;
        #pragma unroll
        for (int ks = 0; ks < 4; ks++) {
            uint32_t afr[4][4];
            #pragma unroll
            for (int im = 0; im < 4; im++) {
                int row = wr + im * 16 + (lane & 15);
                int ch  = ks * 2 + (lane >> 4);
                uint32_t addr = sA + row * 128 + ((uint32_t)(ch ^ (row & 7)) << 4);
                LDSM4(afr[im][0], afr[im][1], afr[im][2], afr[im][3], addr);
            }
            uint32_t bfr[NFR][2];
            #pragma unroll
            for (int ib = 0; ib < NB16; ib++) {
                int row = wc + ib * 16 + ((lane >> 4) << 3) + (lane & 7);
                int ch  = ks * 2 + ((lane >> 3) & 1);
                uint32_t addr = sB + row * 128 + ((uint32_t)(ch ^ (row & 7)) << 4);
                uint32_t r0, r1, r2, r3;
                LDSM4(r0, r1, r2, r3, addr);
                bfr[2*ib][0] = r0; bfr[2*ib][1] = r1;
                bfr[2*ib+1][0] = r2; bfr[2*ib+1][1] = r3;
            }
            #pragma unroll
            for (int im = 0; im < 4; im++)
                #pragma unroll
                for (int in = 0; in < NFR; in++)
                    MMA16816(acc[im][in], afr[im][0], afr[im][1], afr[im][2], afr[im][3],
                             bfr[in][0], bfr[in][1]);
        }
    }

    const int g = lane >> 2, tg = lane & 3;
    const float al = (EPI == 2) ? alpha[0] : 0.f;
    #pragma unroll
    for (int im = 0; im < 4; im++) {
        long r0 = m0 + wr + im * 16 + g;
        float inv0 = 1.f, inv1 = 1.f;
        if (EPI == 3 && do_norm) {
            float ss0 = 0.f, ss1 = 0.f;
            #pragma unroll
            for (int in = 0; in < NFR; in++) {
                ss0 += acc[im][in][0]*acc[im][in][0] + acc[im][in][1]*acc[im][in][1];
                ss1 += acc[im][in][2]*acc[im][in][2] + acc[im][in][3]*acc[im][in][3];
            }
            ss0 += __shfl_xor_sync(0xffffffffu, ss0, 1);
            ss0 += __shfl_xor_sync(0xffffffffu, ss0, 2);
            ss1 += __shfl_xor_sync(0xffffffffu, ss1, 1);
            ss1 += __shfl_xor_sync(0xffffffffu, ss1, 2);
            inv0 = nscale / fmaxf(sqrtf(ss0), 1e-6f);
            inv1 = nscale / fmaxf(sqrtf(ss1), 1e-6f);
        }
        #pragma unroll
        for (int in = 0; in < NFR; in++) {
            long c = n0 + wc + in * 8 + tg * 2;
            float v0 = acc[im][in][0], v1 = acc[im][in][1];
            float v2 = acc[im][in][2], v3 = acc[im][in][3];
            if (EPI == 1) {
                float b0 = bias[c], b1 = bias[c + 1];
                v0 += b0; v1 += b1; v2 += b0; v3 += b1;
                const float is2 = 0.7071067811865475f;
                v0 = 0.5f * v0 * (1.f + erff(v0 * is2));
                v1 = 0.5f * v1 * (1.f + erff(v1 * is2));
                v2 = 0.5f * v2 * (1.f + erff(v2 * is2));
                v3 = 0.5f * v3 * (1.f + erff(v3 * is2));
                *reinterpret_cast<__nv_bfloat162*>(&Cb[r0 * N + c]) =
                    __floats2bfloat162_rn(v0, v1);
                *reinterpret_cast<__nv_bfloat162*>(&Cb[(r0 + 8) * N + c]) =
                    __floats2bfloat162_rn(v2, v3);
            } else if (EPI == 2) {
                float b0 = bias[c], b1 = bias[c + 1];
                float2 ra = *reinterpret_cast<const float2*>(&res[r0 * N + c]);
                float2 rb = *reinterpret_cast<const float2*>(&res[(r0 + 8) * N + c]);
                *reinterpret_cast<float2*>(&Cf[r0 * N + c]) =
                    make_float2(ra.x + al * (v0 + b0), ra.y + al * (v1 + b1));
                *reinterpret_cast<float2*>(&Cf[(r0 + 8) * N + c]) =
                    make_float2(rb.x + al * (v2 + b0), rb.y + al * (v3 + b1));
            } else {  // EPI 3
                *reinterpret_cast<__nv_bfloat162*>(&Cb[r0 * N + c]) =
                    __floats2bfloat162_rn(v0 * inv0, v1 * inv0);
                *reinterpret_cast<__nv_bfloat162*>(&Cb[(r0 + 8) * N + c]) =
                    __floats2bfloat162_rn(v2 * inv1, v3 * inv1);
            }
        }
    }
}

template <int EPI, int BM, int BN>
__global__ __launch_bounds__(BM) void gemm_bf16_kernel(
    const __nv_bfloat16* __restrict__ A, const __nv_bfloat16* __restrict__ W,
    int N, int K,
    const float* __restrict__ bias, const float* __restrict__ res,
    const float* __restrict__ alpha,
    float* __restrict__ Cf, __nv_bfloat16* __restrict__ Cb)
{
    extern __shared__ __align__(1024) char smraw[];
    uint32_t smem = (uint32_t)__cvta_generic_to_shared(smraw);
    long m0 = (long)blockIdx.y * BM;
    long n0 = (long)blockIdx.x * BN;
    gemm_core<EPI, BM, BN>(A, W, N, K, m0, n0, bias, res, alpha, Cf, Cb,
                           false, 1.f, smem);
}

// merged Q/K/V projection, BM=256: grid = 64 (Q) + 256 (K) + 256 (V)
// Q is scaled by 0.5 (= 1/TAU) after l2-norm so attention scores are pre-scaled.
__global__ __launch_bounds__(256) void qkv_gemm_kernel(
    const __nv_bfloat16* __restrict__ qn, const __nv_bfloat16* __restrict__ kvn,
    const __nv_bfloat16* __restrict__ Wqb, const __nv_bfloat16* __restrict__ Wkb,
    const __nv_bfloat16* __restrict__ Wvb,
    __nv_bfloat16* __restrict__ qb, __nv_bfloat16* __restrict__ kb,
    __nv_bfloat16* __restrict__ vb)
{
    extern __shared__ __align__(1024) char smraw[];
    uint32_t smem = (uint32_t)__cvta_generic_to_shared(smraw);

    int bid = blockIdx.x;
    const __nv_bfloat16 *A, *W;
    __nv_bfloat16* C;
    int rel; bool do_norm; float sc;
    if (bid < 64)       { A = qn;  W = Wqb; C = qb; rel = bid;       do_norm = true;  sc = 0.5f; }
    else if (bid < 320) { A = kvn; W = Wkb; C = kb; rel = bid - 64;  do_norm = true;  sc = 1.0f; }
    else                { A = kvn; W = Wvb; C = vb; rel = bid - 320; do_norm = false; sc = 1.0f; }
    long n0 = (long)(rel & 7) << 7;
    long m0 = (long)(rel >> 3) << 8;
    gemm_core<3, 256, 128>(A, W, kDim, kDim, m0, n0, nullptr, nullptr, nullptr,
                           nullptr, C, do_norm, sc, smem);
}

// ---------------------------------------------------------------------------
// Flash attention, NO online softmax: q,k are unit vectors and q carries the
// 1/TAU factor, so scores are in [-0.5, 0.5] -- exp() cannot overflow and
// softmax needs no max subtraction (shift invariance). Exact.
// Grid (B*H, Lq/64), 128 threads.
// ---------------------------------------------------------------------------
__global__ __launch_bounds__(128) void attn_mma_kernel(
    const __nv_bfloat16* __restrict__ q, const __nv_bfloat16* __restrict__ k,
    const __nv_bfloat16* __restrict__ v, __nv_bfloat16* __restrict__ ctx)
{
    __shared__ __align__(1024) unsigned char sm[40 * 1024];
    const uint32_t smem = (uint32_t)__cvta_generic_to_shared(sm);
    const uint32_t sQ = smem;

    const int bh = blockIdx.x;
    const int b = bh >> 4, h = bh & 15;
    const int q0 = blockIdx.y * 64;
    const int tid = threadIdx.x;
    const int lane = tid & 31;
    const int w = tid >> 5;

    const __nv_bfloat16* qg = q + ((size_t)(b * kLq + q0)) * kDim + h * 64;
    const __nv_bfloat16* kg = k + ((size_t)b * kLkv) * kDim + h * 64;
    const __nv_bfloat16* vg = v + ((size_t)b * kLkv) * kDim + h * 64;

    #pragma unroll
    for (int p = 0; p < 4; p++) {
        int idx = tid + p * 128;
        int row = idx >> 3, ch = idx & 7;
        uint32_t doff = row * 128 + ((uint32_t)(ch ^ (row & 7)) << 4);
        CP_ASYNC16(sQ + doff, qg + (size_t)row * kDim + ch * 8);
        CP_ASYNC16(sQ + 8192 + doff, kg + (size_t)row * kDim + ch * 8);
        CP_ASYNC16(sQ + 16384 + doff, vg + (size_t)row * kDim + ch * 8);
    }
    CP_COMMIT();

    uint32_t qa[4][4];
    float oacc[8][4];
    #pragma unroll
    for (int j = 0; j < 8; j++)
        #pragma unroll
        for (int c = 0; c < 4; c++) oacc[j][c] = 0.f;
    float lrow[2] = {0.f, 0.f};

    const int T = kLkv / 64;
    for (int t = 0; t < T; t++) {
        int s = t & 1;
        if (t + 1 < T) {
            uint32_t sK = sQ + 8192 + (s ^ 1) * 16384;
            uint32_t sV = sK + 8192;
            const __nv_bfloat16* kp = kg + (size_t)(t + 1) * 64 * kDim;
            const __nv_bfloat16* vp = vg + (size_t)(t + 1) * 64 * kDim;
            #pragma unroll
            for (int p = 0; p < 4; p++) {
                int idx = tid + p * 128;
                int row = idx >> 3, ch = idx & 7;
                uint32_t doff = row * 128 + ((uint32_t)(ch ^ (row & 7)) << 4);
                CP_ASYNC16(sK + doff, kp + (size_t)row * kDim + ch * 8);
                CP_ASYNC16(sV + doff, vp + (size_t)row * kDim + ch * 8);
            }
            CP_COMMIT();
            asm volatile("cp.async.wait_group 1;");
        } else {
            asm volatile("cp.async.wait_group 0;");
        }
        __syncthreads();

        if (t == 0) {
            #pragma unroll
            for (int ks = 0; ks < 4; ks++) {
                int row = w * 16 + (lane & 15);
                int ch  = ks * 2 + (lane >> 4);
                uint32_t addr = sQ + row * 128 + ((uint32_t)(ch ^ (row & 7)) << 4);
                LDSM4(qa[ks][0], qa[ks][1], qa[ks][2], qa[ks][3], addr);
            }
        }

        uint32_t sK = sQ + 8192 + s * 16384;
        uint32_t sV = sK + 8192;

        float sacc[8][4];
        #pragma unroll
        for (int j = 0; j < 8; j++)
            #pragma unroll
            for (int c = 0; c < 4; c++) sacc[j][c] = 0.f;

        #pragma unroll
        for (int ks = 0; ks < 4; ks++) {
            uint32_t bfr[8][2];
            #pragma unroll
            for (int ib = 0; ib < 4; ib++) {
                int row = ib * 16 + ((lane >> 4) << 3) + (lane & 7);
                int ch  = ks * 2 + ((lane >> 3) & 1);
                uint32_t addr = sK + row * 128 + ((uint32_t)(ch ^ (row & 7)) << 4);
                uint32_t r0, r1, r2, r3;
                LDSM4(r0, r1, r2, r3, addr);
                bfr[2*ib][0] = r0; bfr[2*ib][1] = r1;
                bfr[2*ib+1][0] = r2; bfr[2*ib+1][1] = r3;
            }
            #pragma unroll
            for (int j = 0; j < 8; j++)
                MMA16816(sacc[j], qa[ks][0], qa[ks][1], qa[ks][2], qa[ks][3],
                         bfr[j][0], bfr[j][1]);
        }

        // P = exp(S) directly (S in [-0.5, 0.5]); no max, no rescale.
        float ps0 = 0.f, ps1 = 0.f;
        #pragma unroll
        for (int j = 0; j < 8; j++) {
            sacc[j][0] = __expf(sacc[j][0]);
            sacc[j][1] = __expf(sacc[j][1]);
            sacc[j][2] = __expf(sacc[j][2]);
            sacc[j][3] = __expf(sacc[j][3]);
            ps0 += sacc[j][0] + sacc[j][1];
            ps1 += sacc[j][2] + sacc[j][3];
        }
        lrow[0] += ps0;
        lrow[1] += ps1;

        uint32_t pa[4][4];
        #pragma unroll
        for (int kc = 0; kc < 4; kc++) {
            pa[kc][0] = pack_bf16(sacc[2*kc][0],   sacc[2*kc][1]);
            pa[kc][1] = pack_bf16(sacc[2*kc][2],   sacc[2*kc][3]);
            pa[kc][2] = pack_bf16(sacc[2*kc+1][0], sacc[2*kc+1][1]);
            pa[kc][3] = pack_bf16(sacc[2*kc+1][2], sacc[2*kc+1][3]);
        }

        const int mi = lane >> 3;
        #pragma unroll
        for (int kc = 0; kc < 4; kc++) {
            #pragma unroll
            for (int ng = 0; ng < 4; ng++) {
                int row = kc * 16 + ((mi & 1) << 3) + (lane & 7);
                int ch  = ng * 2 + (mi >> 1);
                uint32_t addr = sV + row * 128 + ((uint32_t)(ch ^ (row & 7)) << 4);
                uint32_t r0, r1, r2, r3;
                LDSM4T(r0, r1, r2, r3, addr);
                MMA16816(oacc[2*ng],   pa[kc][0], pa[kc][1], pa[kc][2], pa[kc][3], r0, r1);
                MMA16816(oacc[2*ng+1], pa[kc][0], pa[kc][1], pa[kc][2], pa[kc][3], r2, r3);
            }
        }
        __syncthreads();
    }

    lrow[0] += __shfl_xor_sync(0xffffffffu, lrow[0], 1);
    lrow[0] += __shfl_xor_sync(0xffffffffu, lrow[0], 2);
    lrow[1] += __shfl_xor_sync(0xffffffffu, lrow[1], 1);
    lrow[1] += __shfl_xor_sync(0xffffffffu, lrow[1], 2);
    float inv0 = 1.0f / lrow[0], inv1 = 1.0f / lrow[1];

    const int g = lane >> 2, tg = lane & 3;
    size_t r0 = (size_t)(b * kLq + q0 + w * 16 + g) * kDim + h * 64;
    #pragma unroll
    for (int j = 0; j < 8; j++) {
        int c = j * 8 + tg * 2;
        *reinterpret_cast<__nv_bfloat162*>(&ctx[r0 + c]) =
            __floats2bfloat162_rn(oacc[j][0] * inv0, oacc[j][1] * inv0);
        *reinterpret_cast<__nv_bfloat162*>(&ctx[r0 + 8 * kDim + c]) =
            __floats2bfloat162_rn(oacc[j][2] * inv1, oacc[j][3] * inv1);
    }
}

// ---------------------------------------------------------------------------
// kernel_launch
// ---------------------------------------------------------------------------
extern "C" void kernel_launch(void* const* d_in, const int* in_sizes, int n_in,
                              void* d_out, int out_size)
{
    const float* q_tokens   = (const float*)d_in[0];
    const float* kv_tokens  = (const float*)d_in[1];
    const float* q_ln_w     = (const float*)d_in[2];
    const float* q_ln_b     = (const float*)d_in[3];
    const float* kv_ln_w    = (const float*)d_in[4];
    const float* kv_ln_b    = (const float*)d_in[5];
    const float* mlp_ln_w   = (const float*)d_in[6];
    const float* mlp_ln_b   = (const float*)d_in[7];
    const float* Wq         = (const float*)d_in[8];
    const float* Wk         = (const float*)d_in[9];
    const float* Wv         = (const float*)d_in[10];
    const float* Wo         = (const float*)d_in[11];
    const float* bo         = (const float*)d_in[12];
    const float* fc1_w      = (const float*)d_in[13];
    const float* fc1_b      = (const float*)d_in[14];
    const float* fc2_w      = (const float*)d_in[15];
    const float* fc2_b      = (const float*)d_in[16];
    const float* alpha_attn = (const float*)d_in[17];
    const float* alpha_mlp  = (const float*)d_in[18];
    float* out = (float*)d_out;

    unsigned char* arena = nullptr;
    cudaGetSymbolAddress((void**)&arena, g_scratch);
    const size_t MB = 1024u * 1024u;

    __nv_bfloat16* qn   = (__nv_bfloat16*)(arena + 0 * MB);
    __nv_bfloat16* kvn  = (__nv_bfloat16*)(arena + 4 * MB);
    __nv_bfloat16* wtb  = (__nv_bfloat16*)(arena + 20 * MB);
    __nv_bfloat16* Wqb  = wtb + 0u * (1u << 20);
    __nv_bfloat16* Wkb  = wtb + 1u * (1u << 20);
    __nv_bfloat16* Wvb  = wtb + 2u * (1u << 20);
    __nv_bfloat16* Wob  = wtb + 3u * (1u << 20);
    __nv_bfloat16* fc1b = wtb + 4u * (1u << 20);
    __nv_bfloat16* fc2b = wtb + 8u * (1u << 20);
    __nv_bfloat16* qb   = (__nv_bfloat16*)(arena + 44 * MB);
    __nv_bfloat16* kb   = (__nv_bfloat16*)(arena + 48 * MB);
    __nv_bfloat16* vb   = (__nv_bfloat16*)(arena + 64 * MB);
    __nv_bfloat16* ctxb = (__nv_bfloat16*)(arena + 80 * MB);
    __nv_bfloat16* hln  = (__nv_bfloat16*)(arena + 84 * MB);
    __nv_bfloat16* h1b  = (__nv_bfloat16*)(arena + 88 * MB);

    constexpr uint32_t kSmem256_128 = 3u * (256u + 128u) * 128u;  // 147456
    constexpr uint32_t kSmem128_64  = 3u * (128u + 64u) * 128u;   // 73728

    cudaFuncSetAttribute(qkv_gemm_kernel,
                         cudaFuncAttributeMaxDynamicSharedMemorySize, kSmem256_128);
    cudaFuncSetAttribute(gemm_bf16_kernel<1,256,128>,
                         cudaFuncAttributeMaxDynamicSharedMemorySize, kSmem256_128);
    cudaFuncSetAttribute(gemm_bf16_kernel<2,128,64>,
                         cudaFuncAttributeMaxDynamicSharedMemorySize, kSmem128_64);

    cvt_all_kernel<<<12288, 256>>>(Wq, Wk, Wv, Wo, fc1_w, fc2_w, wtb);

    ln_qkv_kernel<<<kNQ + kNKV, 256>>>(q_tokens, kv_tokens, q_ln_w, q_ln_b,
                                       kv_ln_w, kv_ln_b, qn, kvn);

    // merged Q/K/V projections (Q: l2norm*0.5; K: l2norm; V: plain)
    qkv_gemm_kernel<<<576, 256, kSmem256_128>>>(qn, kvn, Wqb, Wkb, Wvb, qb, kb, vb);

    attn_mma_kernel<<<dim3(kB * kH, kLq / 64), 128>>>(qb, kb, vb, ctxb);

    // out = q_tokens + alpha_attn * (ctx @ Wo^T + bo)
    gemm_bf16_kernel<2,128,64><<<dim3(kDim / 64, kNQ / 128), 128, kSmem128_64>>>(
        ctxb, Wob, kDim, kDim, bo, q_tokens, alpha_attn, out, nullptr);

    ln_bf16_kernel<<<kNQ, 256>>>(out, mlp_ln_w, mlp_ln_b, hln);

    gemm_bf16_kernel<1,256,128><<<dim3(kMlp / 128, kNQ / 256), 256, kSmem256_128>>>(
        hln, fc1b, kMlp, kDim, fc1_b, nullptr, nullptr, nullptr, h1b);

    // out = out + alpha_mlp * (h1 @ fc2^T + b2)
    gemm_bf16_kernel<2,128,64><<<dim3(kDim / 64, kNQ / 128), 128, kSmem128_64>>>(
        h1b, fc2b, kDim, kMlp, fc2_b, out, alpha_mlp, out, nullptr);
}

// round 14
// speedup vs baseline: 1.0421x; 1.0421x over previous
#include <cuda_runtime.h>
#include <cuda_bf16.h>
#include <cstdint>
#include <math.h>

namespace {
constexpr int kB   = 4;
constexpr int kLq  = 512;
constexpr int kLkv = 2048;
constexpr int kDim = 1024;
constexpr int kH   = 16;
constexpr int kMlp = 4096;
constexpr int kNQ  = kB * kLq;    // 2048
constexpr int kNKV = kB * kLkv;   // 8192
}

__device__ __align__(256) unsigned char g_scratch[160u * 1024u * 1024u];

#define CP_ASYNC16(dst, src) \
    asm volatile("cp.async.cg.shared.global [%0], [%1], 16;" :: "r"(dst), "l"(src))
#define CP_COMMIT() asm volatile("cp.async.commit_group;")
#define LDSM4(r0,r1,r2,r3,addr) \
    asm volatile("ldmatrix.sync.aligned.m8n8.x4.shared.b16 {%0,%1,%2,%3}, [%4];" \
        : "=r"(r0),"=r"(r1),"=r"(r2),"=r"(r3) : "r"(addr))
#define LDSM4T(r0,r1,r2,r3,addr) \
    asm volatile("ldmatrix.sync.aligned.m8n8.x4.trans.shared.b16 {%0,%1,%2,%3}, [%4];" \
        : "=r"(r0),"=r"(r1),"=r"(r2),"=r"(r3) : "r"(addr))
#define MMA16816(d,a0,a1,a2,a3,b0,b1) \
    asm volatile("mma.sync.aligned.m16n8k16.row.col.f32.bf16.bf16.f32 " \
        "{%0,%1,%2,%3}, {%4,%5,%6,%7}, {%8,%9}, {%0,%1,%2,%3};" \
        : "+f"(d[0]),"+f"(d[1]),"+f"(d[2]),"+f"(d[3]) \
        : "r"(a0),"r"(a1),"r"(a2),"r"(a3),"r"(b0),"r"(b1))

__device__ __forceinline__ uint32_t pack_bf16(float a, float b) {
    __nv_bfloat162 t = __floats2bfloat162_rn(a, b);
    return *reinterpret_cast<uint32_t*>(&t);
}

// ---------------------------------------------------------------------------
// Merged f32 -> bf16 weight convert
// ---------------------------------------------------------------------------
__global__ __launch_bounds__(256) void cvt_all_kernel(
    const float* __restrict__ Wq, const float* __restrict__ Wk,
    const float* __restrict__ Wv, const float* __restrict__ Wo,
    const float* __restrict__ fc1, const float* __restrict__ fc2,
    __nv_bfloat16* __restrict__ dst)
{
    const size_t M1 = 1u << 20;
    size_t gid = (size_t)blockIdx.x * 1024 + threadIdx.x * 4;
    const float* src; size_t off;
    if (gid < 4 * M1) {
        int si = (int)(gid >> 20);
        src = (si == 0) ? Wq : (si == 1) ? Wk : (si == 2) ? Wv : Wo;
        off = gid & (M1 - 1);
    } else if (gid < 8 * M1) { src = fc1; off = gid - 4 * M1; }
    else                     { src = fc2; off = gid - 8 * M1; }
    float4 v = *reinterpret_cast<const float4*>(src + off);
    *reinterpret_cast<__nv_bfloat162*>(dst + gid)     = __floats2bfloat162_rn(v.x, v.y);
    *reinterpret_cast<__nv_bfloat162*>(dst + gid + 2) = __floats2bfloat162_rn(v.z, v.w);
}

// ---------------------------------------------------------------------------
// LayerNorm core (fp32 -> bf16), one block per row
// ---------------------------------------------------------------------------
__device__ __forceinline__ void ln_row(
    const float* __restrict__ xr, const float* __restrict__ wv4,
    const float* __restrict__ bv4, __nv_bfloat16* __restrict__ yr)
{
    int t = threadIdx.x;
    float4 xv = reinterpret_cast<const float4*>(xr)[t];
    float s  = xv.x + xv.y + xv.z + xv.w;
    float s2 = xv.x*xv.x + xv.y*xv.y + xv.z*xv.z + xv.w*xv.w;

    #pragma unroll
    for (int off = 16; off > 0; off >>= 1) {
        s  += __shfl_xor_sync(0xffffffffu, s,  off);
        s2 += __shfl_xor_sync(0xffffffffu, s2, off);
    }
    __shared__ float rs[8], rs2[8];
    int wid = t >> 5;
    if ((t & 31) == 0) { rs[wid] = s; rs2[wid] = s2; }
    __syncthreads();
    s = 0.f; s2 = 0.f;
    #pragma unroll
    for (int i = 0; i < 8; i++) { s += rs[i]; s2 += rs2[i]; }

    float mu  = s * (1.0f / kDim);
    float var = s2 * (1.0f / kDim) - mu * mu;
    float r   = rsqrtf(var + 1e-6f);

    float4 wv = reinterpret_cast<const float4*>(wv4)[t];
    float4 bv = reinterpret_cast<const float4*>(bv4)[t];
    reinterpret_cast<__nv_bfloat162*>(yr)[2*t] =
        __floats2bfloat162_rn((xv.x - mu) * r * wv.x + bv.x,
                              (xv.y - mu) * r * wv.y + bv.y);
    reinterpret_cast<__nv_bfloat162*>(yr)[2*t+1] =
        __floats2bfloat162_rn((xv.z - mu) * r * wv.z + bv.z,
                              (xv.w - mu) * r * wv.w + bv.w);
}

__global__ __launch_bounds__(256) void ln_bf16_kernel(
    const float* __restrict__ x, const float* __restrict__ w,
    const float* __restrict__ b, __nv_bfloat16* __restrict__ y)
{
    int row = blockIdx.x;
    ln_row(x + (size_t)row * kDim, w, b, y + (size_t)row * kDim);
}

__global__ __launch_bounds__(256) void ln_qkv_kernel(
    const float* __restrict__ qx, const float* __restrict__ kvx,
    const float* __restrict__ qw, const float* __restrict__ qb_,
    const float* __restrict__ kvw, const float* __restrict__ kvb,
    __nv_bfloat16* __restrict__ qy, __nv_bfloat16* __restrict__ kvy)
{
    int row = blockIdx.x;
    if (row < kNQ) {
        ln_row(qx + (size_t)row * kDim, qw, qb_, qy + (size_t)row * kDim);
    } else {
        int r = row - kNQ;
        ln_row(kvx + (size_t)r * kDim, kvw, kvb, kvy + (size_t)r * kDim);
    }
}

// ---------------------------------------------------------------------------
// GEMM core: C[.,N] = A @ W^T.  128 threads, 4 warps (2x2), warp tile
// 64 x BN/2, BK=64, 3-stage cp.async, one barrier per k-iter.
// EPI 1: bf16 GELU(acc+bias).  EPI 2: fp32 res + alpha*(acc+bias).
// EPI 3: bf16, per-64-col L2-norm*scale if do_norm else plain.
// ---------------------------------------------------------------------------
template <int EPI, int BN>
__device__ __forceinline__ void gemm_core(
    const __nv_bfloat16* __restrict__ A, const __nv_bfloat16* __restrict__ W,
    int N, int K, long m0, long n0,
    const float* __restrict__ bias, const float* __restrict__ res,
    const float* __restrict__ alpha,
    float* __restrict__ Cf, __nv_bfloat16* __restrict__ Cb,
    bool do_norm, float nscale, uint32_t smem)
{
    constexpr int NW   = BN / 2;
    constexpr int NFR  = NW / 8;
    constexpr int NB16 = NW / 16;
    constexpr uint32_t kStageBytes = (uint32_t)(128 + BN) * 128u;
    constexpr uint32_t kBOff = 128u * 128u;
    constexpr int LITER = (128 + BN) / 16;

    const int tid  = threadIdx.x;
    const int lane = tid & 31;
    const int w    = tid >> 5;
    const int wr   = (w >> 1) * 64;
    const int wc   = (w & 1) * NW;

    const __nv_bfloat16* Ag = A + m0 * K;
    const __nv_bfloat16* Wg = W + n0 * K;

    auto load_tile = [&](int t, int s) {
        uint32_t sA = smem + (uint32_t)s * kStageBytes;
        uint32_t sB = sA + kBOff;
        const __nv_bfloat16* a = Ag + (long)t * 64;
        const __nv_bfloat16* b = Wg + (long)t * 64;
        #pragma unroll
        for (int p = 0; p < LITER; p++) {
            int idx = tid + p * 128;
            int row = idx >> 3, ch = idx & 7;
            if (row < 128) {
                uint32_t doff = row * 128 + ((uint32_t)(ch ^ (row & 7)) << 4);
                CP_ASYNC16(sA + doff, a + (long)row * K + ch * 8);
            } else {
                int r = row - 128;
                uint32_t doff = r * 128 + ((uint32_t)(ch ^ (r & 7)) << 4);
                CP_ASYNC16(sB + doff, b + (long)r * K + ch * 8);
            }
        }
    };

    float acc[4][NFR][4];
    #pragma unroll
    for (int i = 0; i < 4; i++)
        #pragma unroll
        for (int j = 0; j < NFR; j++)
            #pragma unroll
            for (int c = 0; c < 4; c++) acc[i][j][c] = 0.f;

    const int T = K >> 6;

    load_tile(0, 0); CP_COMMIT();
    load_tile(1, 1); CP_COMMIT();

    for (int kt = 0; kt < T; kt++) {
        int s = kt % 3;
        asm volatile("cp.async.wait_group 1;" ::: "memory");
        __syncthreads();

        if (kt + 2 < T) load_tile(kt + 2, (kt + 2) % 3);
        CP_COMMIT();

        uint32_t sA = smem + (uint32_t)s * kStageBytes;
        uint32_t sB = sA + kBOff;
        #pragma unroll
        for (int ks = 0; ks < 4; ks++) {
            uint32_t afr[4][4];
            #pragma unroll
            for (int im = 0; im < 4; im++) {
                int row = wr + im * 16 + (lane & 15);
                int ch  = ks * 2 + (lane >> 4);
                uint32_t addr = sA + row * 128 + ((uint32_t)(ch ^ (row & 7)) << 4);
                LDSM4(afr[im][0], afr[im][1], afr[im][2], afr[im][3], addr);
            }
            uint32_t bfr[NFR][2];
            #pragma unroll
            for (int ib = 0; ib < NB16; ib++) {
                int row = wc + ib * 16 + ((lane >> 4) << 3) + (lane & 7);
                int ch  = ks * 2 + ((lane >> 3) & 1);
                uint32_t addr = sB + row * 128 + ((uint32_t)(ch ^ (row & 7)) << 4);
                uint32_t r0, r1, r2, r3;
                LDSM4(r0, r1, r2, r3, addr);
                bfr[2*ib][0] = r0; bfr[2*ib][1] = r1;
                bfr[2*ib+1][0] = r2; bfr[2*ib+1][1] = r3;
            }
            #pragma unroll
            for (int im = 0; im < 4; im++)
                #pragma unroll
                for (int in = 0; in < NFR; in++)
                    MMA16816(acc[im][in], afr[im][0], afr[im][1], afr[im][2], afr[im][3],
                             bfr[in][0], bfr[in][1]);
        }
    }

    const int g = lane >> 2, tg = lane & 3;
    const float al = (EPI == 2) ? alpha[0] : 0.f;
    #pragma unroll
    for (int im = 0; im < 4; im++) {
        long r0 = m0 + wr + im * 16 + g;
        float inv0 = 1.f, inv1 = 1.f;
        if (EPI == 3 && do_norm) {
            float ss0 = 0.f, ss1 = 0.f;
            #pragma unroll
            for (int in = 0; in < NFR; in++) {
                ss0 += acc[im][in][0]*acc[im][in][0] + acc[im][in][1]*acc[im][in][1];
                ss1 += acc[im][in][2]*acc[im][in][2] + acc[im][in][3]*acc[im][in][3];
            }
            ss0 += __shfl_xor_sync(0xffffffffu, ss0, 1);
            ss0 += __shfl_xor_sync(0xffffffffu, ss0, 2);
            ss1 += __shfl_xor_sync(0xffffffffu, ss1, 1);
            ss1 += __shfl_xor_sync(0xffffffffu, ss1, 2);
            inv0 = nscale / fmaxf(sqrtf(ss0), 1e-6f);
            inv1 = nscale / fmaxf(sqrtf(ss1), 1e-6f);
        }
        #pragma unroll
        for (int in = 0; in < NFR; in++) {
            long c = n0 + wc + in * 8 + tg * 2;
            float v0 = acc[im][in][0], v1 = acc[im][in][1];
            float v2 = acc[im][in][2], v3 = acc[im][in][3];
            if (EPI == 1) {
                float b0 = bias[c], b1 = bias[c + 1];
                v0 += b0; v1 += b1; v2 += b0; v3 += b1;
                const float is2 = 0.7071067811865475f;
                v0 = 0.5f * v0 * (1.f + erff(v0 * is2));
                v1 = 0.5f * v1 * (1.f + erff(v1 * is2));
                v2 = 0.5f * v2 * (1.f + erff(v2 * is2));
                v3 = 0.5f * v3 * (1.f + erff(v3 * is2));
                *reinterpret_cast<__nv_bfloat162*>(&Cb[r0 * N + c]) =
                    __floats2bfloat162_rn(v0, v1);
                *reinterpret_cast<__nv_bfloat162*>(&Cb[(r0 + 8) * N + c]) =
                    __floats2bfloat162_rn(v2, v3);
            } else if (EPI == 2) {
                float b0 = bias[c], b1 = bias[c + 1];
                float2 ra = *reinterpret_cast<const float2*>(&res[r0 * N + c]);
                float2 rb = *reinterpret_cast<const float2*>(&res[(r0 + 8) * N + c]);
                *reinterpret_cast<float2*>(&Cf[r0 * N + c]) =
                    make_float2(ra.x + al * (v0 + b0), ra.y + al * (v1 + b1));
                *reinterpret_cast<float2*>(&Cf[(r0 + 8) * N + c]) =
                    make_float2(rb.x + al * (v2 + b0), rb.y + al * (v3 + b1));
            } else {  // EPI 3
                *reinterpret_cast<__nv_bfloat162*>(&Cb[r0 * N + c]) =
                    __floats2bfloat162_rn(v0 * inv0, v1 * inv0);
                *reinterpret_cast<__nv_bfloat162*>(&Cb[(r0 + 8) * N + c]) =
                    __floats2bfloat162_rn(v2 * inv1, v3 * inv1);
            }
        }
    }
}

template <int EPI, int BN>
__global__ __launch_bounds__(128) void gemm_bf16_kernel(
    const __nv_bfloat16* __restrict__ A, const __nv_bfloat16* __restrict__ W,
    int N, int K,
    const float* __restrict__ bias, const float* __restrict__ res,
    const float* __restrict__ alpha,
    float* __restrict__ Cf, __nv_bfloat16* __restrict__ Cb)
{
    extern __shared__ __align__(1024) char smraw[];
    uint32_t smem = (uint32_t)__cvta_generic_to_shared(smraw);
    long m0 = (long)blockIdx.y << 7;
    long n0 = (long)blockIdx.x * BN;
    gemm_core<EPI, BN>(A, W, N, K, m0, n0, bias, res, alpha, Cf, Cb,
                       false, 1.f, smem);
}

// merged Q/K/V projection (BM=128): grid = 128 (Q) + 512 (K) + 512 (V)
// Q is scaled by 0.5 (= 1/TAU) after l2-norm so attention scores come pre-scaled.
__global__ __launch_bounds__(128) void qkv_gemm_kernel(
    const __nv_bfloat16* __restrict__ qn, const __nv_bfloat16* __restrict__ kvn,
    const __nv_bfloat16* __restrict__ Wqb, const __nv_bfloat16* __restrict__ Wkb,
    const __nv_bfloat16* __restrict__ Wvb,
    __nv_bfloat16* __restrict__ qb, __nv_bfloat16* __restrict__ kb,
    __nv_bfloat16* __restrict__ vb)
{
    extern __shared__ __align__(1024) char smraw[];
    uint32_t smem = (uint32_t)__cvta_generic_to_shared(smraw);

    int bid = blockIdx.x;
    const __nv_bfloat16 *A, *W;
    __nv_bfloat16* C;
    int rel; bool do_norm; float sc;
    if (bid < 128)      { A = qn;  W = Wqb; C = qb; rel = bid;       do_norm = true;  sc = 0.5f; }
    else if (bid < 640) { A = kvn; W = Wkb; C = kb; rel = bid - 128; do_norm = true;  sc = 1.0f; }
    else                { A = kvn; W = Wvb; C = vb; rel = bid - 640; do_norm = false; sc = 1.0f; }
    long n0 = (long)(rel & 7) << 7;
    long m0 = (long)(rel >> 3) << 7;
    gemm_core<3, 128>(A, W, kDim, kDim, m0, n0, nullptr, nullptr, nullptr,
                      nullptr, C, do_norm, sc, smem);
}

// ---------------------------------------------------------------------------
// Flash attention, NO online softmax: q,k are unit vectors and q carries the
// 1/TAU factor, so scores are in [-0.5, 0.5] -- exp() cannot overflow and
// softmax needs no max subtraction (shift invariance). Exact.
// Grid (B*H, Lq/64), 128 threads.
// ---------------------------------------------------------------------------
__global__ __launch_bounds__(128) void attn_mma_kernel(
    const __nv_bfloat16* __restrict__ q, const __nv_bfloat16* __restrict__ k,
    const __nv_bfloat16* __restrict__ v, __nv_bfloat16* __restrict__ ctx)
{
    __shared__ __align__(1024) unsigned char sm[40 * 1024];
    const uint32_t smem = (uint32_t)__cvta_generic_to_shared(sm);
    const uint32_t sQ = smem;

    const int bh = blockIdx.x;
    const int b = bh >> 4, h = bh & 15;
    const int q0 = blockIdx.y * 64;
    const int tid = threadIdx.x;
    const int lane = tid & 31;
    const int w = tid >> 5;

    const __nv_bfloat16* qg = q + ((size_t)(b * kLq + q0)) * kDim + h * 64;
    const __nv_bfloat16* kg = k + ((size_t)b * kLkv) * kDim + h * 64;
    const __nv_bfloat16* vg = v + ((size_t)b * kLkv) * kDim + h * 64;

    #pragma unroll
    for (int p = 0; p < 4; p++) {
        int idx = tid + p * 128;
        int row = idx >> 3, ch = idx & 7;
        uint32_t doff = row * 128 + ((uint32_t)(ch ^ (row & 7)) << 4);
        CP_ASYNC16(sQ + doff, qg + (size_t)row * kDim + ch * 8);
        CP_ASYNC16(sQ + 8192 + doff, kg + (size_t)row * kDim + ch * 8);
        CP_ASYNC16(sQ + 16384 + doff, vg + (size_t)row * kDim + ch * 8);
    }
    CP_COMMIT();

    uint32_t qa[4][4];
    float oacc[8][4];
    #pragma unroll
    for (int j = 0; j < 8; j++)
        #pragma unroll
        for (int c = 0; c < 4; c++) oacc[j][c] = 0.f;
    float lrow[2] = {0.f, 0.f};

    const int T = kLkv / 64;
    for (int t = 0; t < T; t++) {
        int s = t & 1;
        if (t + 1 < T) {
            uint32_t sK = sQ + 8192 + (s ^ 1) * 16384;
            uint32_t sV = sK + 8192;
            const __nv_bfloat16* kp = kg + (size_t)(t + 1) * 64 * kDim;
            const __nv_bfloat16* vp = vg + (size_t)(t + 1) * 64 * kDim;
            #pragma unroll
            for (int p = 0; p < 4; p++) {
                int idx = tid + p * 128;
                int row = idx >> 3, ch = idx & 7;
                uint32_t doff = row * 128 + ((uint32_t)(ch ^ (row & 7)) << 4);
                CP_ASYNC16(sK + doff, kp + (size_t)row * kDim + ch * 8);
                CP_ASYNC16(sV + doff, vp + (size_t)row * kDim + ch * 8);
            }
            CP_COMMIT();
            asm volatile("cp.async.wait_group 1;");
        } else {
            asm volatile("cp.async.wait_group 0;");
        }
        __syncthreads();

        if (t == 0) {
            #pragma unroll
            for (int ks = 0; ks < 4; ks++) {
                int row = w * 16 + (lane & 15);
                int ch  = ks * 2 + (lane >> 4);
                uint32_t addr = sQ + row * 128 + ((uint32_t)(ch ^ (row & 7)) << 4);
                LDSM4(qa[ks][0], qa[ks][1], qa[ks][2], qa[ks][3], addr);
            }
        }

        uint32_t sK = sQ + 8192 + s * 16384;
        uint32_t sV = sK + 8192;

        float sacc[8][4];
        #pragma unroll
        for (int j = 0; j < 8; j++)
            #pragma unroll
            for (int c = 0; c < 4; c++) sacc[j][c] = 0.f;

        #pragma unroll
        for (int ks = 0; ks < 4; ks++) {
            uint32_t bfr[8][2];
            #pragma unroll
            for (int ib = 0; ib < 4; ib++) {
                int row = ib * 16 + ((lane >> 4) << 3) + (lane & 7);
                int ch  = ks * 2 + ((lane >> 3) & 1);
                uint32_t addr = sK + row * 128 + ((uint32_t)(ch ^ (row & 7)) << 4);
                uint32_t r0, r1, r2, r3;
                LDSM4(r0, r1, r2, r3, addr);
                bfr[2*ib][0] = r0; bfr[2*ib][1] = r1;
                bfr[2*ib+1][0] = r2; bfr[2*ib+1][1] = r3;
            }
            #pragma unroll
            for (int j = 0; j < 8; j++)
                MMA16816(sacc[j], qa[ks][0], qa[ks][1], qa[ks][2], qa[ks][3],
                         bfr[j][0], bfr[j][1]);
        }

        // P = exp(S) directly (S in [-0.5, 0.5]); no max, no rescale.
        float ps0 = 0.f, ps1 = 0.f;
        #pragma unroll
        for (int j = 0; j < 8; j++) {
            sacc[j][0] = __expf(sacc[j][0]);
            sacc[j][1] = __expf(sacc[j][1]);
            sacc[j][2] = __expf(sacc[j][2]);
            sacc[j][3] = __expf(sacc[j][3]);
            ps0 += sacc[j][0] + sacc[j][1];
            ps1 += sacc[j][2] + sacc[j][3];
        }
        lrow[0] += ps0;
        lrow[1] += ps1;

        uint32_t pa[4][4];
        #pragma unroll
        for (int kc = 0; kc < 4; kc++) {
            pa[kc][0] = pack_bf16(sacc[2*kc][0],   sacc[2*kc][1]);
            pa[kc][1] = pack_bf16(sacc[2*kc][2],   sacc[2*kc][3]);
            pa[kc][2] = pack_bf16(sacc[2*kc+1][0], sacc[2*kc+1][1]);
            pa[kc][3] = pack_bf16(sacc[2*kc+1][2], sacc[2*kc+1][3]);
        }

        const int mi = lane >> 3;
        #pragma unroll
        for (int kc = 0; kc < 4; kc++) {
            #pragma unroll
            for (int ng = 0; ng < 4; ng++) {
                int row = kc * 16 + ((mi & 1) << 3) + (lane & 7);
                int ch  = ng * 2 + (mi >> 1);
                uint32_t addr = sV + row * 128 + ((uint32_t)(ch ^ (row & 7)) << 4);
                uint32_t r0, r1, r2, r3;
                LDSM4T(r0, r1, r2, r3, addr);
                MMA16816(oacc[2*ng],   pa[kc][0], pa[kc][1], pa[kc][2], pa[kc][3], r0, r1);
                MMA16816(oacc[2*ng+1], pa[kc][0], pa[kc][1], pa[kc][2], pa[kc][3], r2, r3);
            }
        }
        __syncthreads();
    }

    lrow[0] += __shfl_xor_sync(0xffffffffu, lrow[0], 1);
    lrow[0] += __shfl_xor_sync(0xffffffffu, lrow[0], 2);
    lrow[1] += __shfl_xor_sync(0xffffffffu, lrow[1], 1);
    lrow[1] += __shfl_xor_sync(0xffffffffu, lrow[1], 2);
    float inv0 = 1.0f / lrow[0], inv1 = 1.0f / lrow[1];

    const int g = lane >> 2, tg = lane & 3;
    size_t r0 = (size_t)(b * kLq + q0 + w * 16 + g) * kDim + h * 64;
    #pragma unroll
    for (int j = 0; j < 8; j++) {
        int c = j * 8 + tg * 2;
        *reinterpret_cast<__nv_bfloat162*>(&ctx[r0 + c]) =
            __floats2bfloat162_rn(oacc[j][0] * inv0, oacc[j][1] * inv0);
        *reinterpret_cast<__nv_bfloat162*>(&ctx[r0 + 8 * kDim + c]) =
            __floats2bfloat162_rn(oacc[j][2] * inv1, oacc[j][3] * inv1);
    }
}

// ---------------------------------------------------------------------------
// kernel_launch
// ---------------------------------------------------------------------------
extern "C" void kernel_launch(void* const* d_in, const int* in_sizes, int n_in,
                              void* d_out, int out_size)
{
    const float* q_tokens   = (const float*)d_in[0];
    const float* kv_tokens  = (const float*)d_in[1];
    const float* q_ln_w     = (const float*)d_in[2];
    const float* q_ln_b     = (const float*)d_in[3];
    const float* kv_ln_w    = (const float*)d_in[4];
    const float* kv_ln_b    = (const float*)d_in[5];
    const float* mlp_ln_w   = (const float*)d_in[6];
    const float* mlp_ln_b   = (const float*)d_in[7];
    const float* Wq         = (const float*)d_in[8];
    const float* Wk         = (const float*)d_in[9];
    const float* Wv         = (const float*)d_in[10];
    const float* Wo         = (const float*)d_in[11];
    const float* bo         = (const float*)d_in[12];
    const float* fc1_w      = (const float*)d_in[13];
    const float* fc1_b      = (const float*)d_in[14];
    const float* fc2_w      = (const float*)d_in[15];
    const float* fc2_b      = (const float*)d_in[16];
    const float* alpha_attn = (const float*)d_in[17];
    const float* alpha_mlp  = (const float*)d_in[18];
    float* out = (float*)d_out;

    unsigned char* arena = nullptr;
    cudaGetSymbolAddress((void**)&arena, g_scratch);
    const size_t MB = 1024u * 1024u;

    __nv_bfloat16* qn   = (__nv_bfloat16*)(arena + 0 * MB);
    __nv_bfloat16* kvn  = (__nv_bfloat16*)(arena + 4 * MB);
    __nv_bfloat16* wtb  = (__nv_bfloat16*)(arena + 20 * MB);
    __nv_bfloat16* Wqb  = wtb + 0u * (1u << 20);
    __nv_bfloat16* Wkb  = wtb + 1u * (1u << 20);
    __nv_bfloat16* Wvb  = wtb + 2u * (1u << 20);
    __nv_bfloat16* Wob  = wtb + 3u * (1u << 20);
    __nv_bfloat16* fc1b = wtb + 4u * (1u << 20);
    __nv_bfloat16* fc2b = wtb + 8u * (1u << 20);
    __nv_bfloat16* qb   = (__nv_bfloat16*)(arena + 44 * MB);
    __nv_bfloat16* kb   = (__nv_bfloat16*)(arena + 48 * MB);
    __nv_bfloat16* vb   = (__nv_bfloat16*)(arena + 64 * MB);
    __nv_bfloat16* ctxb = (__nv_bfloat16*)(arena + 80 * MB);
    __nv_bfloat16* hln  = (__nv_bfloat16*)(arena + 84 * MB);
    __nv_bfloat16* h1b  = (__nv_bfloat16*)(arena + 88 * MB);

    constexpr uint32_t kSmem128 = 3u * (128u + 128u) * 128u;  // 98304
    constexpr uint32_t kSmem64  = 3u * (128u + 64u) * 128u;   // 73728

    cudaFuncSetAttribute(qkv_gemm_kernel,
                         cudaFuncAttributeMaxDynamicSharedMemorySize, kSmem128);
    cudaFuncSetAttribute(gemm_bf16_kernel<1,128>,
                         cudaFuncAttributeMaxDynamicSharedMemorySize, kSmem128);
    cudaFuncSetAttribute(gemm_bf16_kernel<2,64>,
                         cudaFuncAttributeMaxDynamicSharedMemorySize, kSmem64);

    cvt_all_kernel<<<12288, 256>>>(Wq, Wk, Wv, Wo, fc1_w, fc2_w, wtb);

    ln_qkv_kernel<<<kNQ + kNKV, 256>>>(q_tokens, kv_tokens, q_ln_w, q_ln_b,
                                       kv_ln_w, kv_ln_b, qn, kvn);

    // merged Q/K/V projections (Q: l2norm*0.5; K: l2norm; V: plain)
    qkv_gemm_kernel<<<1152, 128, kSmem128>>>(qn, kvn, Wqb, Wkb, Wvb, qb, kb, vb);

    attn_mma_kernel<<<dim3(kB * kH, kLq / 64), 128>>>(qb, kb, vb, ctxb);

    // out = q_tokens + alpha_attn * (ctx @ Wo^T + bo)
    gemm_bf16_kernel<2,64><<<dim3(kDim / 64, kNQ / 128), 128, kSmem64>>>(
        ctxb, Wob, kDim, kDim, bo, q_tokens, alpha_attn, out, nullptr);

    ln_bf16_kernel<<<kNQ, 256>>>(out, mlp_ln_w, mlp_ln_b, hln);

    gemm_bf16_kernel<1,128><<<dim3(kMlp / 128, kNQ / 128), 128, kSmem128>>>(
        hln, fc1b, kMlp, kDim, fc1_b, nullptr, nullptr, nullptr, h1b);

    // out = out + alpha_mlp * (h1 @ fc2^T + b2)
    gemm_bf16_kernel<2,64><<<dim3(kDim / 64, kNQ / 128), 128, kSmem64>>>(
        h1b, fc2b, kDim, kMlp, fc2_b, out, alpha_mlp, out, nullptr);
}

// round 15
// speedup vs baseline: 1.0822x; 1.0384x over previous
#include <cuda_runtime.h>
#include <cuda_bf16.h>
#include <cstdint>
#include <math.h>

namespace {
constexpr int kB   = 4;
constexpr int kLq  = 512;
constexpr int kLkv = 2048;
constexpr int kDim = 1024;
constexpr int kH   = 16;
constexpr int kMlp = 4096;
constexpr int kNQ  = kB * kLq;    // 2048
constexpr int kNKV = kB * kLkv;   // 8192
}

__device__ __align__(256) unsigned char g_scratch[160u * 1024u * 1024u];

#define CP_ASYNC16(dst, src) \
    asm volatile("cp.async.cg.shared.global [%0], [%1], 16;" :: "r"(dst), "l"(src))
#define CP_COMMIT() asm volatile("cp.async.commit_group;")
#define LDSM4(r0,r1,r2,r3,addr) \
    asm volatile("ldmatrix.sync.aligned.m8n8.x4.shared.b16 {%0,%1,%2,%3}, [%4];" \
        : "=r"(r0),"=r"(r1),"=r"(r2),"=r"(r3) : "r"(addr))
#define LDSM4T(r0,r1,r2,r3,addr) \
    asm volatile("ldmatrix.sync.aligned.m8n8.x4.trans.shared.b16 {%0,%1,%2,%3}, [%4];" \
        : "=r"(r0),"=r"(r1),"=r"(r2),"=r"(r3) : "r"(addr))
#define MMA16816(d,a0,a1,a2,a3,b0,b1) \
    asm volatile("mma.sync.aligned.m16n8k16.row.col.f32.bf16.bf16.f32 " \
        "{%0,%1,%2,%3}, {%4,%5,%6,%7}, {%8,%9}, {%0,%1,%2,%3};" \
        : "+f"(d[0]),"+f"(d[1]),"+f"(d[2]),"+f"(d[3]) \
        : "r"(a0),"r"(a1),"r"(a2),"r"(a3),"r"(b0),"r"(b1))
#define HFMA2BF(d,x,a,c) \
    asm("fma.rn.bf16x2 %0, %1, %2, %3;" : "=r"(d) : "r"(x), "r"(a), "r"(c))

__device__ __forceinline__ uint32_t pack_bf16(float a, float b) {
    __nv_bfloat162 t = __floats2bfloat162_rn(a, b);
    return *reinterpret_cast<uint32_t*>(&t);
}

// ---------------------------------------------------------------------------
// Merged f32 -> bf16 weight convert
// ---------------------------------------------------------------------------
__global__ __launch_bounds__(256) void cvt_all_kernel(
    const float* __restrict__ Wq, const float* __restrict__ Wk,
    const float* __restrict__ Wv, const float* __restrict__ Wo,
    const float* __restrict__ fc1, const float* __restrict__ fc2,
    __nv_bfloat16* __restrict__ dst)
{
    const size_t M1 = 1u << 20;
    size_t gid = (size_t)blockIdx.x * 1024 + threadIdx.x * 4;
    const float* src; size_t off;
    if (gid < 4 * M1) {
        int si = (int)(gid >> 20);
        src = (si == 0) ? Wq : (si == 1) ? Wk : (si == 2) ? Wv : Wo;
        off = gid & (M1 - 1);
    } else if (gid < 8 * M1) { src = fc1; off = gid - 4 * M1; }
    else                     { src = fc2; off = gid - 8 * M1; }
    float4 v = *reinterpret_cast<const float4*>(src + off);
    *reinterpret_cast<__nv_bfloat162*>(dst + gid)     = __floats2bfloat162_rn(v.x, v.y);
    *reinterpret_cast<__nv_bfloat162*>(dst + gid + 2) = __floats2bfloat162_rn(v.z, v.w);
}

// ---------------------------------------------------------------------------
// LayerNorm core (fp32 -> bf16), one block per row
// ---------------------------------------------------------------------------
__device__ __forceinline__ void ln_row(
    const float* __restrict__ xr, const float* __restrict__ wv4,
    const float* __restrict__ bv4, __nv_bfloat16* __restrict__ yr)
{
    int t = threadIdx.x;
    float4 xv = reinterpret_cast<const float4*>(xr)[t];
    float s  = xv.x + xv.y + xv.z + xv.w;
    float s2 = xv.x*xv.x + xv.y*xv.y + xv.z*xv.z + xv.w*xv.w;

    #pragma unroll
    for (int off = 16; off > 0; off >>= 1) {
        s  += __shfl_xor_sync(0xffffffffu, s,  off);
        s2 += __shfl_xor_sync(0xffffffffu, s2, off);
    }
    __shared__ float rs[8], rs2[8];
    int wid = t >> 5;
    if ((t & 31) == 0) { rs[wid] = s; rs2[wid] = s2; }
    __syncthreads();
    s = 0.f; s2 = 0.f;
    #pragma unroll
    for (int i = 0; i < 8; i++) { s += rs[i]; s2 += rs2[i]; }

    float mu  = s * (1.0f / kDim);
    float var = s2 * (1.0f / kDim) - mu * mu;
    float r   = rsqrtf(var + 1e-6f);

    float4 wv = reinterpret_cast<const float4*>(wv4)[t];
    float4 bv = reinterpret_cast<const float4*>(bv4)[t];
    reinterpret_cast<__nv_bfloat162*>(yr)[2*t] =
        __floats2bfloat162_rn((xv.x - mu) * r * wv.x + bv.x,
                              (xv.y - mu) * r * wv.y + bv.y);
    reinterpret_cast<__nv_bfloat162*>(yr)[2*t+1] =
        __floats2bfloat162_rn((xv.z - mu) * r * wv.z + bv.z,
                              (xv.w - mu) * r * wv.w + bv.w);
}

__global__ __launch_bounds__(256) void ln_bf16_kernel(
    const float* __restrict__ x, const float* __restrict__ w,
    const float* __restrict__ b, __nv_bfloat16* __restrict__ y)
{
    int row = blockIdx.x;
    ln_row(x + (size_t)row * kDim, w, b, y + (size_t)row * kDim);
}

__global__ __launch_bounds__(256) void ln_qkv_kernel(
    const float* __restrict__ qx, const float* __restrict__ kvx,
    const float* __restrict__ qw, const float* __restrict__ qb_,
    const float* __restrict__ kvw, const float* __restrict__ kvb,
    __nv_bfloat16* __restrict__ qy, __nv_bfloat16* __restrict__ kvy)
{
    int row = blockIdx.x;
    if (row < kNQ) {
        ln_row(qx + (size_t)row * kDim, qw, qb_, qy + (size_t)row * kDim);
    } else {
        int r = row - kNQ;
        ln_row(kvx + (size_t)r * kDim, kvw, kvb, kvy + (size_t)r * kDim);
    }
}

// ---------------------------------------------------------------------------
// GEMM core: C[.,N] = A @ W^T.  128 threads, 4 warps (2x2), warp tile
// 64 x BN/2, BK=64, 3-stage cp.async, one barrier per k-iter.
// EPI 1: bf16 GELU(acc+bias).  EPI 2: fp32 res + alpha*(acc+bias).
// EPI 3: bf16, per-64-col L2-norm*scale if do_norm else plain.
// ---------------------------------------------------------------------------
template <int EPI, int BN>
__device__ __forceinline__ void gemm_core(
    const __nv_bfloat16* __restrict__ A, const __nv_bfloat16* __restrict__ W,
    int N, int K, long m0, long n0,
    const float* __restrict__ bias, const float* __restrict__ res,
    const float* __restrict__ alpha,
    float* __restrict__ Cf, __nv_bfloat16* __restrict__ Cb,
    bool do_norm, float nscale, uint32_t smem)
{
    constexpr int NW   = BN / 2;
    constexpr int NFR  = NW / 8;
    constexpr int NB16 = NW / 16;
    constexpr uint32_t kStageBytes = (uint32_t)(128 + BN) * 128u;
    constexpr uint32_t kBOff = 128u * 128u;
    constexpr int LITER = (128 + BN) / 16;

    const int tid  = threadIdx.x;
    const int lane = tid & 31;
    const int w    = tid >> 5;
    const int wr   = (w >> 1) * 64;
    const int wc   = (w & 1) * NW;

    const __nv_bfloat16* Ag = A + m0 * K;
    const __nv_bfloat16* Wg = W + n0 * K;

    auto load_tile = [&](int t, int s) {
        uint32_t sA = smem + (uint32_t)s * kStageBytes;
        uint32_t sB = sA + kBOff;
        const __nv_bfloat16* a = Ag + (long)t * 64;
        const __nv_bfloat16* b = Wg + (long)t * 64;
        #pragma unroll
        for (int p = 0; p < LITER; p++) {
            int idx = tid + p * 128;
            int row = idx >> 3, ch = idx & 7;
            if (row < 128) {
                uint32_t doff = row * 128 + ((uint32_t)(ch ^ (row & 7)) << 4);
                CP_ASYNC16(sA + doff, a + (long)row * K + ch * 8);
            } else {
                int r = row - 128;
                uint32_t doff = r * 128 + ((uint32_t)(ch ^ (r & 7)) << 4);
                CP_ASYNC16(sB + doff, b + (long)r * K + ch * 8);
            }
        }
    };

    float acc[4][NFR][4];
    #pragma unroll
    for (int i = 0; i < 4; i++)
        #pragma unroll
        for (int j = 0; j < NFR; j++)
            #pragma unroll
            for (int c = 0; c < 4; c++) acc[i][j][c] = 0.f;

    const int T = K >> 6;

    load_tile(0, 0); CP_COMMIT();
    load_tile(1, 1); CP_COMMIT();

    for (int kt = 0; kt < T; kt++) {
        int s = kt % 3;
        asm volatile("cp.async.wait_group 1;" ::: "memory");
        __syncthreads();

        if (kt + 2 < T) load_tile(kt + 2, (kt + 2) % 3);
        CP_COMMIT();

        uint32_t sA = smem + (uint32_t)s * kStageBytes;
        uint32_t sB = sA + kBOff;
        #pragma unroll
        for (int ks = 0; ks < 4; ks++) {
            uint32_t afr[4][4];
            #pragma unroll
            for (int im = 0; im < 4; im++) {
                int row = wr + im * 16 + (lane & 15);
                int ch  = ks * 2 + (lane >> 4);
                uint32_t addr = sA + row * 128 + ((uint32_t)(ch ^ (row & 7)) << 4);
                LDSM4(afr[im][0], afr[im][1], afr[im][2], afr[im][3], addr);
            }
            uint32_t bfr[NFR][2];
            #pragma unroll
            for (int ib = 0; ib < NB16; ib++) {
                int row = wc + ib * 16 + ((lane >> 4) << 3) + (lane & 7);
                int ch  = ks * 2 + ((lane >> 3) & 1);
                uint32_t addr = sB + row * 128 + ((uint32_t)(ch ^ (row & 7)) << 4);
                uint32_t r0, r1, r2, r3;
                LDSM4(r0, r1, r2, r3, addr);
                bfr[2*ib][0] = r0; bfr[2*ib][1] = r1;
                bfr[2*ib+1][0] = r2; bfr[2*ib+1][1] = r3;
            }
            #pragma unroll
            for (int im = 0; im < 4; im++)
                #pragma unroll
                for (int in = 0; in < NFR; in++)
                    MMA16816(acc[im][in], afr[im][0], afr[im][1], afr[im][2], afr[im][3],
                             bfr[in][0], bfr[in][1]);
        }
    }

    const int g = lane >> 2, tg = lane & 3;
    const float al = (EPI == 2) ? alpha[0] : 0.f;
    #pragma unroll
    for (int im = 0; im < 4; im++) {
        long r0 = m0 + wr + im * 16 + g;
        float inv0 = 1.f, inv1 = 1.f;
        if (EPI == 3 && do_norm) {
            float ss0 = 0.f, ss1 = 0.f;
            #pragma unroll
            for (int in = 0; in < NFR; in++) {
                ss0 += acc[im][in][0]*acc[im][in][0] + acc[im][in][1]*acc[im][in][1];
                ss1 += acc[im][in][2]*acc[im][in][2] + acc[im][in][3]*acc[im][in][3];
            }
            ss0 += __shfl_xor_sync(0xffffffffu, ss0, 1);
            ss0 += __shfl_xor_sync(0xffffffffu, ss0, 2);
            ss1 += __shfl_xor_sync(0xffffffffu, ss1, 1);
            ss1 += __shfl_xor_sync(0xffffffffu, ss1, 2);
            inv0 = nscale / fmaxf(sqrtf(ss0), 1e-6f);
            inv1 = nscale / fmaxf(sqrtf(ss1), 1e-6f);
        }
        #pragma unroll
        for (int in = 0; in < NFR; in++) {
            long c = n0 + wc + in * 8 + tg * 2;
            float v0 = acc[im][in][0], v1 = acc[im][in][1];
            float v2 = acc[im][in][2], v3 = acc[im][in][3];
            if (EPI == 1) {
                float b0 = bias[c], b1 = bias[c + 1];
                v0 += b0; v1 += b1; v2 += b0; v3 += b1;
                const float is2 = 0.7071067811865475f;
                v0 = 0.5f * v0 * (1.f + erff(v0 * is2));
                v1 = 0.5f * v1 * (1.f + erff(v1 * is2));
                v2 = 0.5f * v2 * (1.f + erff(v2 * is2));
                v3 = 0.5f * v3 * (1.f + erff(v3 * is2));
                *reinterpret_cast<__nv_bfloat162*>(&Cb[r0 * N + c]) =
                    __floats2bfloat162_rn(v0, v1);
                *reinterpret_cast<__nv_bfloat162*>(&Cb[(r0 + 8) * N + c]) =
                    __floats2bfloat162_rn(v2, v3);
            } else if (EPI == 2) {
                float b0 = bias[c], b1 = bias[c + 1];
                float2 ra = *reinterpret_cast<const float2*>(&res[r0 * N + c]);
                float2 rb = *reinterpret_cast<const float2*>(&res[(r0 + 8) * N + c]);
                *reinterpret_cast<float2*>(&Cf[r0 * N + c]) =
                    make_float2(ra.x + al * (v0 + b0), ra.y + al * (v1 + b1));
                *reinterpret_cast<float2*>(&Cf[(r0 + 8) * N + c]) =
                    make_float2(rb.x + al * (v2 + b0), rb.y + al * (v3 + b1));
            } else {  // EPI 3
                *reinterpret_cast<__nv_bfloat162*>(&Cb[r0 * N + c]) =
                    __floats2bfloat162_rn(v0 * inv0, v1 * inv0);
                *reinterpret_cast<__nv_bfloat162*>(&Cb[(r0 + 8) * N + c]) =
                    __floats2bfloat162_rn(v2 * inv1, v3 * inv1);
            }
        }
    }
}

template <int EPI, int BN>
__global__ __launch_bounds__(128) void gemm_bf16_kernel(
    const __nv_bfloat16* __restrict__ A, const __nv_bfloat16* __restrict__ W,
    int N, int K,
    const float* __restrict__ bias, const float* __restrict__ res,
    const float* __restrict__ alpha,
    float* __restrict__ Cf, __nv_bfloat16* __restrict__ Cb)
{
    extern __shared__ __align__(1024) char smraw[];
    uint32_t smem = (uint32_t)__cvta_generic_to_shared(smraw);
    long m0 = (long)blockIdx.y << 7;
    long n0 = (long)blockIdx.x * BN;
    gemm_core<EPI, BN>(A, W, N, K, m0, n0, bias, res, alpha, Cf, Cb,
                       false, 1.f, smem);
}

// merged Q/K/V projection (BM=128): grid = 128 (Q) + 512 (K) + 512 (V)
// Q is scaled by 0.5 (= 1/TAU) after l2-norm so attention scores come pre-scaled.
__global__ __launch_bounds__(128) void qkv_gemm_kernel(
    const __nv_bfloat16* __restrict__ qn, const __nv_bfloat16* __restrict__ kvn,
    const __nv_bfloat16* __restrict__ Wqb, const __nv_bfloat16* __restrict__ Wkb,
    const __nv_bfloat16* __restrict__ Wvb,
    __nv_bfloat16* __restrict__ qb, __nv_bfloat16* __restrict__ kb,
    __nv_bfloat16* __restrict__ vb)
{
    extern __shared__ __align__(1024) char smraw[];
    uint32_t smem = (uint32_t)__cvta_generic_to_shared(smraw);

    int bid = blockIdx.x;
    const __nv_bfloat16 *A, *W;
    __nv_bfloat16* C;
    int rel; bool do_norm; float sc;
    if (bid < 128)      { A = qn;  W = Wqb; C = qb; rel = bid;       do_norm = true;  sc = 0.5f; }
    else if (bid < 640) { A = kvn; W = Wkb; C = kb; rel = bid - 128; do_norm = true;  sc = 1.0f; }
    else                { A = kvn; W = Wvb; C = vb; rel = bid - 640; do_norm = false; sc = 1.0f; }
    long n0 = (long)(rel & 7) << 7;
    long m0 = (long)(rel >> 3) << 7;
    gemm_core<3, 128>(A, W, kDim, kDim, m0, n0, nullptr, nullptr, nullptr,
                      nullptr, C, do_norm, sc, smem);
}

// ---------------------------------------------------------------------------
// Flash attention. Scores in [-0.5, 0.5] (unit q,k; 1/TAU folded into q), so:
//   - no max subtraction (shift-invariant softmax, no overflow possible)
//   - exp computed as a Chebyshev cubic IN PACKED bf16x2 (fma.rn.bf16x2),
//     2 values/op on the FMA pipe instead of 1/op on the rt=8 MUFU pipe.
//     Poly rel-err ~5e-4 < bf16 quantization of P (4e-3) already present.
//   - row sums (softmax denominator) via an extra ones-column MMA: exact fp32
//     accumulation of the SAME bf16 P used in the numerator; kills the FADD
//     chain and the end-of-kernel shuffles.
// Grid (B*H, Lq/64), 128 threads.
// ---------------------------------------------------------------------------
__global__ __launch_bounds__(128) void attn_mma_kernel(
    const __nv_bfloat16* __restrict__ q, const __nv_bfloat16* __restrict__ k,
    const __nv_bfloat16* __restrict__ v, __nv_bfloat16* __restrict__ ctx)
{
    __shared__ __align__(1024) unsigned char sm[40 * 1024];
    const uint32_t smem = (uint32_t)__cvta_generic_to_shared(sm);
    const uint32_t sQ = smem;

    const int bh = blockIdx.x;
    const int b = bh >> 4, h = bh & 15;
    const int q0 = blockIdx.y * 64;
    const int tid = threadIdx.x;
    const int lane = tid & 31;
    const int w = tid >> 5;

    const __nv_bfloat16* qg = q + ((size_t)(b * kLq + q0)) * kDim + h * 64;
    const __nv_bfloat16* kg = k + ((size_t)b * kLkv) * kDim + h * 64;
    const __nv_bfloat16* vg = v + ((size_t)b * kLkv) * kDim + h * 64;

    #pragma unroll
    for (int p = 0; p < 4; p++) {
        int idx = tid + p * 128;
        int row = idx >> 3, ch = idx & 7;
        uint32_t doff = row * 128 + ((uint32_t)(ch ^ (row & 7)) << 4);
        CP_ASYNC16(sQ + doff, qg + (size_t)row * kDim + ch * 8);
        CP_ASYNC16(sQ + 8192 + doff, kg + (size_t)row * kDim + ch * 8);
        CP_ASYNC16(sQ + 16384 + doff, vg + (size_t)row * kDim + ch * 8);
    }
    CP_COMMIT();

    // exp() cubic coefficients, packed bf16x2 (hoisted by the compiler)
    const uint32_t C_ONE = 0x3F803F80u;                    // (1.0, 1.0)
    const uint32_t C2 = pack_bf16(0.51056f, 0.51056f);
    const uint32_t C3 = pack_bf16(0.16928f, 0.16928f);

    uint32_t qa[4][4];
    float oacc[8][4];
    #pragma unroll
    for (int j = 0; j < 8; j++)
        #pragma unroll
        for (int c = 0; c < 4; c++) oacc[j][c] = 0.f;
    float sumacc[4] = {0.f, 0.f, 0.f, 0.f};   // ones-MMA denominator C-frag

    const int T = kLkv / 64;
    for (int t = 0; t < T; t++) {
        int s = t & 1;
        if (t + 1 < T) {
            uint32_t sK = sQ + 8192 + (s ^ 1) * 16384;
            uint32_t sV = sK + 8192;
            const __nv_bfloat16* kp = kg + (size_t)(t + 1) * 64 * kDim;
            const __nv_bfloat16* vp = vg + (size_t)(t + 1) * 64 * kDim;
            #pragma unroll
            for (int p = 0; p < 4; p++) {
                int idx = tid + p * 128;
                int row = idx >> 3, ch = idx & 7;
                uint32_t doff = row * 128 + ((uint32_t)(ch ^ (row & 7)) << 4);
                CP_ASYNC16(sK + doff, kp + (size_t)row * kDim + ch * 8);
                CP_ASYNC16(sV + doff, vp + (size_t)row * kDim + ch * 8);
            }
            CP_COMMIT();
            asm volatile("cp.async.wait_group 1;");
        } else {
            asm volatile("cp.async.wait_group 0;");
        }
        __syncthreads();

        if (t == 0) {
            #pragma unroll
            for (int ks = 0; ks < 4; ks++) {
                int row = w * 16 + (lane & 15);
                int ch  = ks * 2 + (lane >> 4);
                uint32_t addr = sQ + row * 128 + ((uint32_t)(ch ^ (row & 7)) << 4);
                LDSM4(qa[ks][0], qa[ks][1], qa[ks][2], qa[ks][3], addr);
            }
        }

        uint32_t sK = sQ + 8192 + s * 16384;
        uint32_t sV = sK + 8192;

        float sacc[8][4];
        #pragma unroll
        for (int j = 0; j < 8; j++)
            #pragma unroll
            for (int c = 0; c < 4; c++) sacc[j][c] = 0.f;

        #pragma unroll
        for (int ks = 0; ks < 4; ks++) {
            uint32_t bfr[8][2];
            #pragma unroll
            for (int ib = 0; ib < 4; ib++) {
                int row = ib * 16 + ((lane >> 4) << 3) + (lane & 7);
                int ch  = ks * 2 + ((lane >> 3) & 1);
                uint32_t addr = sK + row * 128 + ((uint32_t)(ch ^ (row & 7)) << 4);
                uint32_t r0, r1, r2, r3;
                LDSM4(r0, r1, r2, r3, addr);
                bfr[2*ib][0] = r0; bfr[2*ib][1] = r1;
                bfr[2*ib+1][0] = r2; bfr[2*ib+1][1] = r3;
            }
            #pragma unroll
            for (int j = 0; j < 8; j++)
                MMA16816(sacc[j], qa[ks][0], qa[ks][1], qa[ks][2], qa[ks][3],
                         bfr[j][0], bfr[j][1]);
        }

        // pack scores to bf16x2 (A-frag layout), then exp via cubic HFMA2
        uint32_t pa[4][4];
        #pragma unroll
        for (int kc = 0; kc < 4; kc++) {
            pa[kc][0] = pack_bf16(sacc[2*kc][0],   sacc[2*kc][1]);
            pa[kc][1] = pack_bf16(sacc[2*kc][2],   sacc[2*kc][3]);
            pa[kc][2] = pack_bf16(sacc[2*kc+1][0], sacc[2*kc+1][1]);
            pa[kc][3] = pack_bf16(sacc[2*kc+1][2], sacc[2*kc+1][3]);
        }
        #pragma unroll
        for (int kc = 0; kc < 4; kc++)
            #pragma unroll
            for (int r = 0; r < 4; r++) {
                uint32_t x = pa[kc][r], tpoly;
                HFMA2BF(tpoly, x, C3, C2);       // c2 + x*c3
                HFMA2BF(tpoly, x, tpoly, C_ONE); // 1 + x*(...)
                HFMA2BF(tpoly, x, tpoly, C_ONE); // 1 + x*(...)
                pa[kc][r] = tpoly;
            }

        // O += P V ; denominator += P * ones
        const int mi = lane >> 3;
        #pragma unroll
        for (int kc = 0; kc < 4; kc++) {
            MMA16816(sumacc, pa[kc][0], pa[kc][1], pa[kc][2], pa[kc][3],
                     C_ONE, C_ONE);
            #pragma unroll
            for (int ng = 0; ng < 4; ng++) {
                int row = kc * 16 + ((mi & 1) << 3) + (lane & 7);
                int ch  = ng * 2 + (mi >> 1);
                uint32_t addr = sV + row * 128 + ((uint32_t)(ch ^ (row & 7)) << 4);
                uint32_t r0, r1, r2, r3;
                LDSM4T(r0, r1, r2, r3, addr);
                MMA16816(oacc[2*ng],   pa[kc][0], pa[kc][1], pa[kc][2], pa[kc][3], r0, r1);
                MMA16816(oacc[2*ng+1], pa[kc][0], pa[kc][1], pa[kc][2], pa[kc][3], r2, r3);
            }
        }
        __syncthreads();
    }

    // sumacc cols are all equal to the row sum: c0 -> row g, c2 -> row g+8
    float inv0 = 1.0f / sumacc[0], inv1 = 1.0f / sumacc[2];

    const int g = lane >> 2, tg = lane & 3;
    size_t r0 = (size_t)(b * kLq + q0 + w * 16 + g) * kDim + h * 64;
    #pragma unroll
    for (int j = 0; j < 8; j++) {
        int c = j * 8 + tg * 2;
        *reinterpret_cast<__nv_bfloat162*>(&ctx[r0 + c]) =
            __floats2bfloat162_rn(oacc[j][0] * inv0, oacc[j][1] * inv0);
        *reinterpret_cast<__nv_bfloat162*>(&ctx[r0 + 8 * kDim + c]) =
            __floats2bfloat162_rn(oacc[j][2] * inv1, oacc[j][3] * inv1);
    }
}

// ---------------------------------------------------------------------------
// kernel_launch
// ---------------------------------------------------------------------------
extern "C" void kernel_launch(void* const* d_in, const int* in_sizes, int n_in,
                              void* d_out, int out_size)
{
    const float* q_tokens   = (const float*)d_in[0];
    const float* kv_tokens  = (const float*)d_in[1];
    const float* q_ln_w     = (const float*)d_in[2];
    const float* q_ln_b     = (const float*)d_in[3];
    const float* kv_ln_w    = (const float*)d_in[4];
    const float* kv_ln_b    = (const float*)d_in[5];
    const float* mlp_ln_w   = (const float*)d_in[6];
    const float* mlp_ln_b   = (const float*)d_in[7];
    const float* Wq         = (const float*)d_in[8];
    const float* Wk         = (const float*)d_in[9];
    const float* Wv         = (const float*)d_in[10];
    const float* Wo         = (const float*)d_in[11];
    const float* bo         = (const float*)d_in[12];
    const float* fc1_w      = (const float*)d_in[13];
    const float* fc1_b      = (const float*)d_in[14];
    const float* fc2_w      = (const float*)d_in[15];
    const float* fc2_b      = (const float*)d_in[16];
    const float* alpha_attn = (const float*)d_in[17];
    const float* alpha_mlp  = (const float*)d_in[18];
    float* out = (float*)d_out;

    unsigned char* arena = nullptr;
    cudaGetSymbolAddress((void**)&arena, g_scratch);
    const size_t MB = 1024u * 1024u;

    __nv_bfloat16* qn   = (__nv_bfloat16*)(arena + 0 * MB);
    __nv_bfloat16* kvn  = (__nv_bfloat16*)(arena + 4 * MB);
    __nv_bfloat16* wtb  = (__nv_bfloat16*)(arena + 20 * MB);
    __nv_bfloat16* Wqb  = wtb + 0u * (1u << 20);
    __nv_bfloat16* Wkb  = wtb + 1u * (1u << 20);
    __nv_bfloat16* Wvb  = wtb + 2u * (1u << 20);
    __nv_bfloat16* Wob  = wtb + 3u * (1u << 20);
    __nv_bfloat16* fc1b = wtb + 4u * (1u << 20);
    __nv_bfloat16* fc2b = wtb + 8u * (1u << 20);
    __nv_bfloat16* qb   = (__nv_bfloat16*)(arena + 44 * MB);
    __nv_bfloat16* kb   = (__nv_bfloat16*)(arena + 48 * MB);
    __nv_bfloat16* vb   = (__nv_bfloat16*)(arena + 64 * MB);
    __nv_bfloat16* ctxb = (__nv_bfloat16*)(arena + 80 * MB);
    __nv_bfloat16* hln  = (__nv_bfloat16*)(arena + 84 * MB);
    __nv_bfloat16* h1b  = (__nv_bfloat16*)(arena + 88 * MB);

    constexpr uint32_t kSmem128 = 3u * (128u + 128u) * 128u;  // 98304
    constexpr uint32_t kSmem64  = 3u * (128u + 64u) * 128u;   // 73728

    cudaFuncSetAttribute(qkv_gemm_kernel,
                         cudaFuncAttributeMaxDynamicSharedMemorySize, kSmem128);
    cudaFuncSetAttribute(gemm_bf16_kernel<1,128>,
                         cudaFuncAttributeMaxDynamicSharedMemorySize, kSmem128);
    cudaFuncSetAttribute(gemm_bf16_kernel<2,64>,
                         cudaFuncAttributeMaxDynamicSharedMemorySize, kSmem64);

    cvt_all_kernel<<<12288, 256>>>(Wq, Wk, Wv, Wo, fc1_w, fc2_w, wtb);

    ln_qkv_kernel<<<kNQ + kNKV, 256>>>(q_tokens, kv_tokens, q_ln_w, q_ln_b,
                                       kv_ln_w, kv_ln_b, qn, kvn);

    // merged Q/K/V projections (Q: l2norm*0.5; K: l2norm; V: plain)
    qkv_gemm_kernel<<<1152, 128, kSmem128>>>(qn, kvn, Wqb, Wkb, Wvb, qb, kb, vb);

    attn_mma_kernel<<<dim3(kB * kH, kLq / 64), 128>>>(qb, kb, vb, ctxb);

    // out = q_tokens + alpha_attn * (ctx @ Wo^T + bo)
    gemm_bf16_kernel<2,64><<<dim3(kDim / 64, kNQ / 128), 128, kSmem64>>>(
        ctxb, Wob, kDim, kDim, bo, q_tokens, alpha_attn, out, nullptr);

    ln_bf16_kernel<<<kNQ, 256>>>(out, mlp_ln_w, mlp_ln_b, hln);

    gemm_bf16_kernel<1,128><<<dim3(kMlp / 128, kNQ / 128), 128, kSmem128>>>(
        hln, fc1b, kMlp, kDim, fc1_b, nullptr, nullptr, nullptr, h1b);

    // out = out + alpha_mlp * (h1 @ fc2^T + b2)
    gemm_bf16_kernel<2,64><<<dim3(kDim / 64, kNQ / 128), 128, kSmem64>>>(
        h1b, fc2b, kDim, kMlp, fc2_b, out, alpha_mlp, out, nullptr);
}

// round 16
// speedup vs baseline: 1.0890x; 1.0063x over previous
#include <cuda_runtime.h>
#include <cuda_bf16.h>
#include <cstdint>
#include <math.h>

namespace {
constexpr int kB   = 4;
constexpr int kLq  = 512;
constexpr int kLkv = 2048;
constexpr int kDim = 1024;
constexpr int kH   = 16;
constexpr int kMlp = 4096;
constexpr int kNQ  = kB * kLq;    // 2048
constexpr int kNKV = kB * kLkv;   // 8192
constexpr int kSplits = 2;        // KV splits for attention
constexpr int kLsStride = kNQ * kH;             // lsum elems per split
constexpr size_t kOpStride = (size_t)kNQ * kDim; // numerator elems per split
}

__device__ __align__(256) unsigned char g_scratch[160u * 1024u * 1024u];

#define CP_ASYNC16(dst, src) \
    asm volatile("cp.async.cg.shared.global [%0], [%1], 16;" :: "r"(dst), "l"(src))
#define CP_COMMIT() asm volatile("cp.async.commit_group;")
#define LDSM4(r0,r1,r2,r3,addr) \
    asm volatile("ldmatrix.sync.aligned.m8n8.x4.shared.b16 {%0,%1,%2,%3}, [%4];" \
        : "=r"(r0),"=r"(r1),"=r"(r2),"=r"(r3) : "r"(addr))
#define LDSM4T(r0,r1,r2,r3,addr) \
    asm volatile("ldmatrix.sync.aligned.m8n8.x4.trans.shared.b16 {%0,%1,%2,%3}, [%4];" \
        : "=r"(r0),"=r"(r1),"=r"(r2),"=r"(r3) : "r"(addr))
#define MMA16816(d,a0,a1,a2,a3,b0,b1) \
    asm volatile("mma.sync.aligned.m16n8k16.row.col.f32.bf16.bf16.f32 " \
        "{%0,%1,%2,%3}, {%4,%5,%6,%7}, {%8,%9}, {%0,%1,%2,%3};" \
        : "+f"(d[0]),"+f"(d[1]),"+f"(d[2]),"+f"(d[3]) \
        : "r"(a0),"r"(a1),"r"(a2),"r"(a3),"r"(b0),"r"(b1))
#define HFMA2BF(d,x,a,c) \
    asm("fma.rn.bf16x2 %0, %1, %2, %3;" : "=r"(d) : "r"(x), "r"(a), "r"(c))

__device__ __forceinline__ uint32_t pack_bf16(float a, float b) {
    __nv_bfloat162 t = __floats2bfloat162_rn(a, b);
    return *reinterpret_cast<uint32_t*>(&t);
}

// ---------------------------------------------------------------------------
// Merged f32 -> bf16 weight convert
// ---------------------------------------------------------------------------
__global__ __launch_bounds__(256) void cvt_all_kernel(
    const float* __restrict__ Wq, const float* __restrict__ Wk,
    const float* __restrict__ Wv, const float* __restrict__ Wo,
    const float* __restrict__ fc1, const float* __restrict__ fc2,
    __nv_bfloat16* __restrict__ dst)
{
    const size_t M1 = 1u << 20;
    size_t gid = (size_t)blockIdx.x * 1024 + threadIdx.x * 4;
    const float* src; size_t off;
    if (gid < 4 * M1) {
        int si = (int)(gid >> 20);
        src = (si == 0) ? Wq : (si == 1) ? Wk : (si == 2) ? Wv : Wo;
        off = gid & (M1 - 1);
    } else if (gid < 8 * M1) { src = fc1; off = gid - 4 * M1; }
    else                     { src = fc2; off = gid - 8 * M1; }
    float4 v = *reinterpret_cast<const float4*>(src + off);
    *reinterpret_cast<__nv_bfloat162*>(dst + gid)     = __floats2bfloat162_rn(v.x, v.y);
    *reinterpret_cast<__nv_bfloat162*>(dst + gid + 2) = __floats2bfloat162_rn(v.z, v.w);
}

// ---------------------------------------------------------------------------
// LayerNorm core (fp32 -> bf16), one block per row
// ---------------------------------------------------------------------------
__device__ __forceinline__ void ln_row(
    const float* __restrict__ xr, const float* __restrict__ wv4,
    const float* __restrict__ bv4, __nv_bfloat16* __restrict__ yr)
{
    int t = threadIdx.x;
    float4 xv = reinterpret_cast<const float4*>(xr)[t];
    float s  = xv.x + xv.y + xv.z + xv.w;
    float s2 = xv.x*xv.x + xv.y*xv.y + xv.z*xv.z + xv.w*xv.w;

    #pragma unroll
    for (int off = 16; off > 0; off >>= 1) {
        s  += __shfl_xor_sync(0xffffffffu, s,  off);
        s2 += __shfl_xor_sync(0xffffffffu, s2, off);
    }
    __shared__ float rs[8], rs2[8];
    int wid = t >> 5;
    if ((t & 31) == 0) { rs[wid] = s; rs2[wid] = s2; }
    __syncthreads();
    s = 0.f; s2 = 0.f;
    #pragma unroll
    for (int i = 0; i < 8; i++) { s += rs[i]; s2 += rs2[i]; }

    float mu  = s * (1.0f / kDim);
    float var = s2 * (1.0f / kDim) - mu * mu;
    float r   = rsqrtf(var + 1e-6f);

    float4 wv = reinterpret_cast<const float4*>(wv4)[t];
    float4 bv = reinterpret_cast<const float4*>(bv4)[t];
    reinterpret_cast<__nv_bfloat162*>(yr)[2*t] =
        __floats2bfloat162_rn((xv.x - mu) * r * wv.x + bv.x,
                              (xv.y - mu) * r * wv.y + bv.y);
    reinterpret_cast<__nv_bfloat162*>(yr)[2*t+1] =
        __floats2bfloat162_rn((xv.z - mu) * r * wv.z + bv.z,
                              (xv.w - mu) * r * wv.w + bv.w);
}

__global__ __launch_bounds__(256) void ln_bf16_kernel(
    const float* __restrict__ x, const float* __restrict__ w,
    const float* __restrict__ b, __nv_bfloat16* __restrict__ y)
{
    int row = blockIdx.x;
    ln_row(x + (size_t)row * kDim, w, b, y + (size_t)row * kDim);
}

__global__ __launch_bounds__(256) void ln_qkv_kernel(
    const float* __restrict__ qx, const float* __restrict__ kvx,
    const float* __restrict__ qw, const float* __restrict__ qb_,
    const float* __restrict__ kvw, const float* __restrict__ kvb,
    __nv_bfloat16* __restrict__ qy, __nv_bfloat16* __restrict__ kvy)
{
    int row = blockIdx.x;
    if (row < kNQ) {
        ln_row(qx + (size_t)row * kDim, qw, qb_, qy + (size_t)row * kDim);
    } else {
        int r = row - kNQ;
        ln_row(kvx + (size_t)r * kDim, kvw, kvb, kvy + (size_t)r * kDim);
    }
}

// ---------------------------------------------------------------------------
// GEMM core: C[.,N] = A @ W^T.  128 threads, 4 warps (2x2), warp tile
// 64 x BN/2, BK=64, 3-stage cp.async, one barrier per k-iter.
// EPI 1: bf16 GELU(acc+bias).  EPI 2: fp32 res + alpha*(acc+bias).
// EPI 3: bf16, per-64-col L2-norm*scale if do_norm else plain.
// ---------------------------------------------------------------------------
template <int EPI, int BN>
__device__ __forceinline__ void gemm_core(
    const __nv_bfloat16* __restrict__ A, const __nv_bfloat16* __restrict__ W,
    int N, int K, long m0, long n0,
    const float* __restrict__ bias, const float* __restrict__ res,
    const float* __restrict__ alpha,
    float* __restrict__ Cf, __nv_bfloat16* __restrict__ Cb,
    bool do_norm, float nscale, uint32_t smem)
{
    constexpr int NW   = BN / 2;
    constexpr int NFR  = NW / 8;
    constexpr int NB16 = NW / 16;
    constexpr uint32_t kStageBytes = (uint32_t)(128 + BN) * 128u;
    constexpr uint32_t kBOff = 128u * 128u;
    constexpr int LITER = (128 + BN) / 16;

    const int tid  = threadIdx.x;
    const int lane = tid & 31;
    const int w    = tid >> 5;
    const int wr   = (w >> 1) * 64;
    const int wc   = (w & 1) * NW;

    const __nv_bfloat16* Ag = A + m0 * K;
    const __nv_bfloat16* Wg = W + n0 * K;

    auto load_tile = [&](int t, int s) {
        uint32_t sA = smem + (uint32_t)s * kStageBytes;
        uint32_t sB = sA + kBOff;
        const __nv_bfloat16* a = Ag + (long)t * 64;
        const __nv_bfloat16* b = Wg + (long)t * 64;
        #pragma unroll
        for (int p = 0; p < LITER; p++) {
            int idx = tid + p * 128;
            int row = idx >> 3, ch = idx & 7;
            if (row < 128) {
                uint32_t doff = row * 128 + ((uint32_t)(ch ^ (row & 7)) << 4);
                CP_ASYNC16(sA + doff, a + (long)row * K + ch * 8);
            } else {
                int r = row - 128;
                uint32_t doff = r * 128 + ((uint32_t)(ch ^ (r & 7)) << 4);
                CP_ASYNC16(sB + doff, b + (long)r * K + ch * 8);
            }
        }
    };

    float acc[4][NFR][4];
    #pragma unroll
    for (int i = 0; i < 4; i++)
        #pragma unroll
        for (int j = 0; j < NFR; j++)
            #pragma unroll
            for (int c = 0; c < 4; c++) acc[i][j][c] = 0.f;

    const int T = K >> 6;

    load_tile(0, 0); CP_COMMIT();
    load_tile(1, 1); CP_COMMIT();

    for (int kt = 0; kt < T; kt++) {
        int s = kt % 3;
        asm volatile("cp.async.wait_group 1;" ::: "memory");
        __syncthreads();

        if (kt + 2 < T) load_tile(kt + 2, (kt + 2) % 3);
        CP_COMMIT();

        uint32_t sA = smem + (uint32_t)s * kStageBytes;
        uint32_t sB = sA + kBOff;
        #pragma unroll
        for (int ks = 0; ks < 4; ks++) {
            uint32_t afr[4][4];
            #pragma unroll
            for (int im = 0; im < 4; im++) {
                int row = wr + im * 16 + (lane & 15);
                int ch  = ks * 2 + (lane >> 4);
                uint32_t addr = sA + row * 128 + ((uint32_t)(ch ^ (row & 7)) << 4);
                LDSM4(afr[im][0], afr[im][1], afr[im][2], afr[im][3], addr);
            }
            uint32_t bfr[NFR][2];
            #pragma unroll
            for (int ib = 0; ib < NB16; ib++) {
                int row = wc + ib * 16 + ((lane >> 4) << 3) + (lane & 7);
                int ch  = ks * 2 + ((lane >> 3) & 1);
                uint32_t addr = sB + row * 128 + ((uint32_t)(ch ^ (row & 7)) << 4);
                uint32_t r0, r1, r2, r3;
                LDSM4(r0, r1, r2, r3, addr);
                bfr[2*ib][0] = r0; bfr[2*ib][1] = r1;
                bfr[2*ib+1][0] = r2; bfr[2*ib+1][1] = r3;
            }
            #pragma unroll
            for (int im = 0; im < 4; im++)
                #pragma unroll
                for (int in = 0; in < NFR; in++)
                    MMA16816(acc[im][in], afr[im][0], afr[im][1], afr[im][2], afr[im][3],
                             bfr[in][0], bfr[in][1]);
        }
    }

    const int g = lane >> 2, tg = lane & 3;
    const float al = (EPI == 2) ? alpha[0] : 0.f;
    #pragma unroll
    for (int im = 0; im < 4; im++) {
        long r0 = m0 + wr + im * 16 + g;
        float inv0 = 1.f, inv1 = 1.f;
        if (EPI == 3 && do_norm) {
            float ss0 = 0.f, ss1 = 0.f;
            #pragma unroll
            for (int in = 0; in < NFR; in++) {
                ss0 += acc[im][in][0]*acc[im][in][0] + acc[im][in][1]*acc[im][in][1];
                ss1 += acc[im][in][2]*acc[im][in][2] + acc[im][in][3]*acc[im][in][3];
            }
            ss0 += __shfl_xor_sync(0xffffffffu, ss0, 1);
            ss0 += __shfl_xor_sync(0xffffffffu, ss0, 2);
            ss1 += __shfl_xor_sync(0xffffffffu, ss1, 1);
            ss1 += __shfl_xor_sync(0xffffffffu, ss1, 2);
            inv0 = nscale / fmaxf(sqrtf(ss0), 1e-6f);
            inv1 = nscale / fmaxf(sqrtf(ss1), 1e-6f);
        }
        #pragma unroll
        for (int in = 0; in < NFR; in++) {
            long c = n0 + wc + in * 8 + tg * 2;
            float v0 = acc[im][in][0], v1 = acc[im][in][1];
            float v2 = acc[im][in][2], v3 = acc[im][in][3];
            if (EPI == 1) {
                float b0 = bias[c], b1 = bias[c + 1];
                v0 += b0; v1 += b1; v2 += b0; v3 += b1;
                const float is2 = 0.7071067811865475f;
                v0 = 0.5f * v0 * (1.f + erff(v0 * is2));
                v1 = 0.5f * v1 * (1.f + erff(v1 * is2));
                v2 = 0.5f * v2 * (1.f + erff(v2 * is2));
                v3 = 0.5f * v3 * (1.f + erff(v3 * is2));
                *reinterpret_cast<__nv_bfloat162*>(&Cb[r0 * N + c]) =
                    __floats2bfloat162_rn(v0, v1);
                *reinterpret_cast<__nv_bfloat162*>(&Cb[(r0 + 8) * N + c]) =
                    __floats2bfloat162_rn(v2, v3);
            } else if (EPI == 2) {
                float b0 = bias[c], b1 = bias[c + 1];
                float2 ra = *reinterpret_cast<const float2*>(&res[r0 * N + c]);
                float2 rb = *reinterpret_cast<const float2*>(&res[(r0 + 8) * N + c]);
                *reinterpret_cast<float2*>(&Cf[r0 * N + c]) =
                    make_float2(ra.x + al * (v0 + b0), ra.y + al * (v1 + b1));
                *reinterpret_cast<float2*>(&Cf[(r0 + 8) * N + c]) =
                    make_float2(rb.x + al * (v2 + b0), rb.y + al * (v3 + b1));
            } else {  // EPI 3
                *reinterpret_cast<__nv_bfloat162*>(&Cb[r0 * N + c]) =
                    __floats2bfloat162_rn(v0 * inv0, v1 * inv0);
                *reinterpret_cast<__nv_bfloat162*>(&Cb[(r0 + 8) * N + c]) =
                    __floats2bfloat162_rn(v2 * inv1, v3 * inv1);
            }
        }
    }
}

template <int EPI, int BN>
__global__ __launch_bounds__(128) void gemm_bf16_kernel(
    const __nv_bfloat16* __restrict__ A, const __nv_bfloat16* __restrict__ W,
    int N, int K,
    const float* __restrict__ bias, const float* __restrict__ res,
    const float* __restrict__ alpha,
    float* __restrict__ Cf, __nv_bfloat16* __restrict__ Cb)
{
    extern __shared__ __align__(1024) char smraw[];
    uint32_t smem = (uint32_t)__cvta_generic_to_shared(smraw);
    long m0 = (long)blockIdx.y << 7;
    long n0 = (long)blockIdx.x * BN;
    gemm_core<EPI, BN>(A, W, N, K, m0, n0, bias, res, alpha, Cf, Cb,
                       false, 1.f, smem);
}

// merged Q/K/V projection (BM=128): grid = 128 (Q) + 512 (K) + 512 (V)
// Q is scaled by 0.5 (= 1/TAU) after l2-norm so attention scores come pre-scaled.
__global__ __launch_bounds__(128) void qkv_gemm_kernel(
    const __nv_bfloat16* __restrict__ qn, const __nv_bfloat16* __restrict__ kvn,
    const __nv_bfloat16* __restrict__ Wqb, const __nv_bfloat16* __restrict__ Wkb,
    const __nv_bfloat16* __restrict__ Wvb,
    __nv_bfloat16* __restrict__ qb, __nv_bfloat16* __restrict__ kb,
    __nv_bfloat16* __restrict__ vb)
{
    extern __shared__ __align__(1024) char smraw[];
    uint32_t smem = (uint32_t)__cvta_generic_to_shared(smraw);

    int bid = blockIdx.x;
    const __nv_bfloat16 *A, *W;
    __nv_bfloat16* C;
    int rel; bool do_norm; float sc;
    if (bid < 128)      { A = qn;  W = Wqb; C = qb; rel = bid;       do_norm = true;  sc = 0.5f; }
    else if (bid < 640) { A = kvn; W = Wkb; C = kb; rel = bid - 128; do_norm = true;  sc = 1.0f; }
    else                { A = kvn; W = Wvb; C = vb; rel = bid - 640; do_norm = false; sc = 1.0f; }
    long n0 = (long)(rel & 7) << 7;
    long m0 = (long)(rel >> 3) << 7;
    gemm_core<3, 128>(A, W, kDim, kDim, m0, n0, nullptr, nullptr, nullptr,
                      nullptr, C, do_norm, sc, smem);
}

// ---------------------------------------------------------------------------
// Split-KV flash attention. Scores in [-0.5, 0.5] (unit q,k; 1/TAU in q):
//   - no max subtraction needed -> partial results are DIRECTLY ADDITIVE:
//     each split writes unnormalized numerator N_s (fp32) + denominator l_s;
//     combine kernel does (N0+N1)/(l0+l1). Exact.
//   - exp via Chebyshev cubic in packed bf16x2 (FMA pipe, not MUFU)
//   - denominator via ones-column MMA
// Grid (B*H, Lq/64, kSplits), 128 threads.
// ---------------------------------------------------------------------------
__global__ __launch_bounds__(128) void attn_mma_kernel(
    const __nv_bfloat16* __restrict__ q, const __nv_bfloat16* __restrict__ k,
    const __nv_bfloat16* __restrict__ v,
    float* __restrict__ opart, float* __restrict__ lpart)
{
    __shared__ __align__(1024) unsigned char sm[40 * 1024];
    const uint32_t smem = (uint32_t)__cvta_generic_to_shared(sm);
    const uint32_t sQ = smem;

    const int bh = blockIdx.x;
    const int b = bh >> 4, h = bh & 15;
    const int q0 = blockIdx.y * 64;
    const int sp = blockIdx.z;
    const int tid = threadIdx.x;
    const int lane = tid & 31;
    const int w = tid >> 5;

    const int kv0base = sp * (kLkv / kSplits);

    const __nv_bfloat16* qg = q + ((size_t)(b * kLq + q0)) * kDim + h * 64;
    const __nv_bfloat16* kg = k + ((size_t)(b * kLkv + kv0base)) * kDim + h * 64;
    const __nv_bfloat16* vg = v + ((size_t)(b * kLkv + kv0base)) * kDim + h * 64;

    #pragma unroll
    for (int p = 0; p < 4; p++) {
        int idx = tid + p * 128;
        int row = idx >> 3, ch = idx & 7;
        uint32_t doff = row * 128 + ((uint32_t)(ch ^ (row & 7)) << 4);
        CP_ASYNC16(sQ + doff, qg + (size_t)row * kDim + ch * 8);
        CP_ASYNC16(sQ + 8192 + doff, kg + (size_t)row * kDim + ch * 8);
        CP_ASYNC16(sQ + 16384 + doff, vg + (size_t)row * kDim + ch * 8);
    }
    CP_COMMIT();

    const uint32_t C_ONE = 0x3F803F80u;
    const uint32_t C2 = pack_bf16(0.51056f, 0.51056f);
    const uint32_t C3 = pack_bf16(0.16928f, 0.16928f);

    uint32_t qa[4][4];
    float oacc[8][4];
    #pragma unroll
    for (int j = 0; j < 8; j++)
        #pragma unroll
        for (int c = 0; c < 4; c++) oacc[j][c] = 0.f;
    float sumacc[4] = {0.f, 0.f, 0.f, 0.f};

    const int T = kLkv / kSplits / 64;   // 16 tiles total -> 8 per split
    for (int t = 0; t < T; t++) {
        int s = t & 1;
        if (t + 1 < T) {
            uint32_t sK = sQ + 8192 + (s ^ 1) * 16384;
            uint32_t sV = sK + 8192;
            const __nv_bfloat16* kp = kg + (size_t)(t + 1) * 64 * kDim;
            const __nv_bfloat16* vp = vg + (size_t)(t + 1) * 64 * kDim;
            #pragma unroll
            for (int p = 0; p < 4; p++) {
                int idx = tid + p * 128;
                int row = idx >> 3, ch = idx & 7;
                uint32_t doff = row * 128 + ((uint32_t)(ch ^ (row & 7)) << 4);
                CP_ASYNC16(sK + doff, kp + (size_t)row * kDim + ch * 8);
                CP_ASYNC16(sV + doff, vp + (size_t)row * kDim + ch * 8);
            }
            CP_COMMIT();
            asm volatile("cp.async.wait_group 1;");
        } else {
            asm volatile("cp.async.wait_group 0;");
        }
        __syncthreads();

        if (t == 0) {
            #pragma unroll
            for (int ks = 0; ks < 4; ks++) {
                int row = w * 16 + (lane & 15);
                int ch  = ks * 2 + (lane >> 4);
                uint32_t addr = sQ + row * 128 + ((uint32_t)(ch ^ (row & 7)) << 4);
                LDSM4(qa[ks][0], qa[ks][1], qa[ks][2], qa[ks][3], addr);
            }
        }

        uint32_t sK = sQ + 8192 + s * 16384;
        uint32_t sV = sK + 8192;

        float sacc[8][4];
        #pragma unroll
        for (int j = 0; j < 8; j++)
            #pragma unroll
            for (int c = 0; c < 4; c++) sacc[j][c] = 0.f;

        #pragma unroll
        for (int ks = 0; ks < 4; ks++) {
            uint32_t bfr[8][2];
            #pragma unroll
            for (int ib = 0; ib < 4; ib++) {
                int row = ib * 16 + ((lane >> 4) << 3) + (lane & 7);
                int ch  = ks * 2 + ((lane >> 3) & 1);
                uint32_t addr = sK + row * 128 + ((uint32_t)(ch ^ (row & 7)) << 4);
                uint32_t r0, r1, r2, r3;
                LDSM4(r0, r1, r2, r3, addr);
                bfr[2*ib][0] = r0; bfr[2*ib][1] = r1;
                bfr[2*ib+1][0] = r2; bfr[2*ib+1][1] = r3;
            }
            #pragma unroll
            for (int j = 0; j < 8; j++)
                MMA16816(sacc[j], qa[ks][0], qa[ks][1], qa[ks][2], qa[ks][3],
                         bfr[j][0], bfr[j][1]);
        }

        // pack scores -> bf16x2, exp via cubic HFMA2
        uint32_t pa[4][4];
        #pragma unroll
        for (int kc = 0; kc < 4; kc++) {
            pa[kc][0] = pack_bf16(sacc[2*kc][0],   sacc[2*kc][1]);
            pa[kc][1] = pack_bf16(sacc[2*kc][2],   sacc[2*kc][3]);
            pa[kc][2] = pack_bf16(sacc[2*kc+1][0], sacc[2*kc+1][1]);
            pa[kc][3] = pack_bf16(sacc[2*kc+1][2], sacc[2*kc+1][3]);
        }
        #pragma unroll
        for (int kc = 0; kc < 4; kc++)
            #pragma unroll
            for (int r = 0; r < 4; r++) {
                uint32_t x = pa[kc][r], tpoly;
                HFMA2BF(tpoly, x, C3, C2);
                HFMA2BF(tpoly, x, tpoly, C_ONE);
                HFMA2BF(tpoly, x, tpoly, C_ONE);
                pa[kc][r] = tpoly;
            }

        // O += P V ; denominator += P * ones
        const int mi = lane >> 3;
        #pragma unroll
        for (int kc = 0; kc < 4; kc++) {
            MMA16816(sumacc, pa[kc][0], pa[kc][1], pa[kc][2], pa[kc][3],
                     C_ONE, C_ONE);
            #pragma unroll
            for (int ng = 0; ng < 4; ng++) {
                int row = kc * 16 + ((mi & 1) << 3) + (lane & 7);
                int ch  = ng * 2 + (mi >> 1);
                uint32_t addr = sV + row * 128 + ((uint32_t)(ch ^ (row & 7)) << 4);
                uint32_t r0, r1, r2, r3;
                LDSM4T(r0, r1, r2, r3, addr);
                MMA16816(oacc[2*ng],   pa[kc][0], pa[kc][1], pa[kc][2], pa[kc][3], r0, r1);
                MMA16816(oacc[2*ng+1], pa[kc][0], pa[kc][1], pa[kc][2], pa[kc][3], r2, r3);
            }
        }
        __syncthreads();
    }

    // write unnormalized partials (fp32) + denominators
    const int g = lane >> 2, tg = lane & 3;
    const size_t rowA = (size_t)(b * kLq + q0 + w * 16 + g);
    float* op = opart + (size_t)sp * kOpStride + rowA * kDim + h * 64;
    #pragma unroll
    for (int j = 0; j < 8; j++) {
        int c = j * 8 + tg * 2;
        *reinterpret_cast<float2*>(op + c) = make_float2(oacc[j][0], oacc[j][1]);
        *reinterpret_cast<float2*>(op + 8 * kDim + c) = make_float2(oacc[j][2], oacc[j][3]);
    }
    if (tg == 0) {
        lpart[sp * kLsStride + rowA * kH + h]       = sumacc[0];
        lpart[sp * kLsStride + (rowA + 8) * kH + h] = sumacc[2];
    }
}

// combine: ctx[row, c] = (N0 + N1) / (l0 + l1), bf16 out.
// Grid kNQ blocks x 256 threads (4 cols each, one head per thread).
__global__ __launch_bounds__(256) void attn_combine_kernel(
    const float* __restrict__ opart, const float* __restrict__ lpart,
    __nv_bfloat16* __restrict__ ctx)
{
    const size_t row = blockIdx.x;
    const int c0 = threadIdx.x * 4;
    const int h = c0 >> 6;
    float l = lpart[row * kH + h] + lpart[kLsStride + row * kH + h];
    float inv = 1.0f / l;
    float4 a = *reinterpret_cast<const float4*>(opart + row * kDim + c0);
    float4 bb = *reinterpret_cast<const float4*>(opart + kOpStride + row * kDim + c0);
    __nv_bfloat162* dst = reinterpret_cast<__nv_bfloat162*>(ctx + row * kDim + c0);
    dst[0] = __floats2bfloat162_rn((a.x + bb.x) * inv, (a.y + bb.y) * inv);
    dst[1] = __floats2bfloat162_rn((a.z + bb.z) * inv, (a.w + bb.w) * inv);
}

// ---------------------------------------------------------------------------
// kernel_launch
// ---------------------------------------------------------------------------
extern "C" void kernel_launch(void* const* d_in, const int* in_sizes, int n_in,
                              void* d_out, int out_size)
{
    const float* q_tokens   = (const float*)d_in[0];
    const float* kv_tokens  = (const float*)d_in[1];
    const float* q_ln_w     = (const float*)d_in[2];
    const float* q_ln_b     = (const float*)d_in[3];
    const float* kv_ln_w    = (const float*)d_in[4];
    const float* kv_ln_b    = (const float*)d_in[5];
    const float* mlp_ln_w   = (const float*)d_in[6];
    const float* mlp_ln_b   = (const float*)d_in[7];
    const float* Wq         = (const float*)d_in[8];
    const float* Wk         = (const float*)d_in[9];
    const float* Wv         = (const float*)d_in[10];
    const float* Wo         = (const float*)d_in[11];
    const float* bo         = (const float*)d_in[12];
    const float* fc1_w      = (const float*)d_in[13];
    const float* fc1_b      = (const float*)d_in[14];
    const float* fc2_w      = (const float*)d_in[15];
    const float* fc2_b      = (const float*)d_in[16];
    const float* alpha_attn = (const float*)d_in[17];
    const float* alpha_mlp  = (const float*)d_in[18];
    float* out = (float*)d_out;

    unsigned char* arena = nullptr;
    cudaGetSymbolAddress((void**)&arena, g_scratch);
    const size_t MB = 1024u * 1024u;

    __nv_bfloat16* qn   = (__nv_bfloat16*)(arena + 0 * MB);
    __nv_bfloat16* kvn  = (__nv_bfloat16*)(arena + 4 * MB);
    __nv_bfloat16* wtb  = (__nv_bfloat16*)(arena + 20 * MB);
    __nv_bfloat16* Wqb  = wtb + 0u * (1u << 20);
    __nv_bfloat16* Wkb  = wtb + 1u * (1u << 20);
    __nv_bfloat16* Wvb  = wtb + 2u * (1u << 20);
    __nv_bfloat16* Wob  = wtb + 3u * (1u << 20);
    __nv_bfloat16* fc1b = wtb + 4u * (1u << 20);
    __nv_bfloat16* fc2b = wtb + 8u * (1u << 20);
    __nv_bfloat16* qb   = (__nv_bfloat16*)(arena + 44 * MB);
    __nv_bfloat16* kb   = (__nv_bfloat16*)(arena + 48 * MB);
    __nv_bfloat16* vb   = (__nv_bfloat16*)(arena + 64 * MB);
    __nv_bfloat16* ctxb = (__nv_bfloat16*)(arena + 80 * MB);
    __nv_bfloat16* hln  = (__nv_bfloat16*)(arena + 84 * MB);
    __nv_bfloat16* h1b  = (__nv_bfloat16*)(arena + 88 * MB);
    float*         opart = (float*)(arena + 104 * MB);  // 16 MB (2 splits x 8 MB)
    float*         lpart = (float*)(arena + 120 * MB);  // 256 KB

    constexpr uint32_t kSmem128 = 3u * (128u + 128u) * 128u;  // 98304
    constexpr uint32_t kSmem64  = 3u * (128u + 64u) * 128u;   // 73728

    cudaFuncSetAttribute(qkv_gemm_kernel,
                         cudaFuncAttributeMaxDynamicSharedMemorySize, kSmem128);
    cudaFuncSetAttribute(gemm_bf16_kernel<1,128>,
                         cudaFuncAttributeMaxDynamicSharedMemorySize, kSmem128);
    cudaFuncSetAttribute(gemm_bf16_kernel<2,64>,
                         cudaFuncAttributeMaxDynamicSharedMemorySize, kSmem64);

    cvt_all_kernel<<<12288, 256>>>(Wq, Wk, Wv, Wo, fc1_w, fc2_w, wtb);

    ln_qkv_kernel<<<kNQ + kNKV, 256>>>(q_tokens, kv_tokens, q_ln_w, q_ln_b,
                                       kv_ln_w, kv_ln_b, qn, kvn);

    // merged Q/K/V projections (Q: l2norm*0.5; K: l2norm; V: plain)
    qkv_gemm_kernel<<<1152, 128, kSmem128>>>(qn, kvn, Wqb, Wkb, Wvb, qb, kb, vb);

    // split-KV attention + combine
    attn_mma_kernel<<<dim3(kB * kH, kLq / 64, kSplits), 128>>>(qb, kb, vb, opart, lpart);
    attn_combine_kernel<<<kNQ, 256>>>(opart, lpart, ctxb);

    // out = q_tokens + alpha_attn * (ctx @ Wo^T + bo)
    gemm_bf16_kernel<2,64><<<dim3(kDim / 64, kNQ / 128), 128, kSmem64>>>(
        ctxb, Wob, kDim, kDim, bo, q_tokens, alpha_attn, out, nullptr);

    ln_bf16_kernel<<<kNQ, 256>>>(out, mlp_ln_w, mlp_ln_b, hln);

    gemm_bf16_kernel<1,128><<<dim3(kMlp / 128, kNQ / 128), 128, kSmem128>>>(
        hln, fc1b, kMlp, kDim, fc1_b, nullptr, nullptr, nullptr, h1b);

    // out = out + alpha_mlp * (h1 @ fc2^T + b2)
    gemm_bf16_kernel<2,64><<<dim3(kDim / 64, kNQ / 128), 128, kSmem64>>>(
        h1b, fc2b, kDim, kMlp, fc2_b, out, alpha_mlp, out, nullptr);
}